// round 10
// baseline (speedup 1.0000x reference)
#include <cuda_runtime.h>
#include <math.h>
#include <cstdint>

// Problem constants
#define BB 2
#define SS 2048
#define DD 1024
#define HH 16
#define DH 64
#define FF 4096
#define ROWS (BB*SS)          // 4096
#define WINDOW 128
#define NGLOB 16
#define NEGV -1e9f

// weight offsets inside g_wr
#define OFF_WIN  0
#define OFF_WOUT (3*DD*DD)
#define OFF_W1   (OFF_WOUT + DD*DD)
#define OFF_W2   (OFF_W1 + FF*DD)
#define WTOTAL   (OFF_W2 + DD*FF)

// ---------------- scratch ----------------
__device__ float g_hln[ROWS * DD];
__device__ float g_qkv[ROWS * 3 * DD];
__device__ float g_o  [ROWS * DD];
__device__ float g_x1 [ROWS * DD];
__device__ float g_h2 [ROWS * FF];
__device__ float g_wr [WTOTAL];

// ---------------- helpers ----------------
__device__ __forceinline__ float tf32rf(float f) {
    uint32_t u;
    asm("cvt.rna.tf32.f32 %0, %1;" : "=r"(u) : "f"(f));
    return __uint_as_float(u);
}
__device__ __forceinline__ uint32_t smem_u32(const void* p) {
    uint32_t a;
    asm("{ .reg .u64 t; cvta.to.shared.u64 t, %1; cvt.u32.u64 %0, t; }" : "=r"(a) : "l"(p));
    return a;
}
#define CP_ASYNC16(sdst, gsrc) \
    asm volatile("cp.async.cg.shared.global [%0], [%1], 16;" :: "r"(sdst), "l"(gsrc))
#define CP_COMMIT() asm volatile("cp.async.commit_group;" ::: "memory")
#define CP_WAIT1()  asm volatile("cp.async.wait_group 1;" ::: "memory")

#define LDSM_X4(r0, r1, r2, r3, addr) \
    asm volatile("ldmatrix.sync.aligned.m8n8.x4.shared.b16 {%0,%1,%2,%3}, [%4];" \
        : "=r"(r0), "=r"(r1), "=r"(r2), "=r"(r3) : "r"(addr))

#define MMA_TF32(c, a, b) \
    asm volatile("mma.sync.aligned.m16n8k8.row.col.f32.tf32.tf32.f32 " \
        "{%0,%1,%2,%3}, {%4,%5,%6,%7}, {%8,%9}, {%0,%1,%2,%3};" \
        : "+f"((c)[0]), "+f"((c)[1]), "+f"((c)[2]), "+f"((c)[3]) \
        : "r"((a)[0]), "r"((a)[1]), "r"((a)[2]), "r"((a)[3]), \
          "r"((b)[0]), "r"((b)[1]))

// ---------------- weight tf32 pre-round ----------------
__global__ __launch_bounds__(256) void wprep_kernel(const float* __restrict__ w_in,
                                                    const float* __restrict__ w_out,
                                                    const float* __restrict__ w1,
                                                    const float* __restrict__ w2)
{
    long i = ((long)blockIdx.x * 256 + threadIdx.x) * 4;
    float4 v;
    if (i < OFF_WOUT)      v = *(const float4*)(w_in + i);
    else if (i < OFF_W1)   v = *(const float4*)(w_out + (i - OFF_WOUT));
    else if (i < OFF_W2)   v = *(const float4*)(w1 + (i - OFF_W1));
    else                   v = *(const float4*)(w2 + (i - OFF_W2));
    v.x = tf32rf(v.x); v.y = tf32rf(v.y); v.z = tf32rf(v.z); v.w = tf32rf(v.w);
    *(float4*)(g_wr + i) = v;
}

#define RSTR 144                            // smem row stride bytes (36 floats)
#define NSTAGES 3

// ================= GEMM A: 128x128 CTA tile, 4 warps (2Mx2N), warp 64x64 ====
#define STG  (128 * RSTR)
#define GEMM_SMEM (2 * NSTAGES * STG)       // 110592

template <bool GELU, bool RES, bool RTF>
__global__ __launch_bounds__(128, 2) void gemm_mma(const float* __restrict__ A,
                                                   const float* __restrict__ W,
                                                   const float* __restrict__ bias,
                                                   const float* __restrict__ res,
                                                   float* __restrict__ C,
                                                   int M, int N, int K)
{
    extern __shared__ char smem[];
    uint32_t sA = smem_u32(smem);
    uint32_t sB = sA + NSTAGES * STG;

    int tid = threadIdx.x;
    int lane = tid & 31, wid = tid >> 5;
    int m0 = blockIdx.y * 128;
    int n0 = blockIdx.x * 128;
    int wm = (wid & 1) * 64;
    int wn = (wid >> 1) * 64;

    int r0 = tid >> 3;
    int c16 = tid & 7;
    const float* Agp = A + (long)(m0 + r0) * K + c16 * 4;
    const float* Bgp = W + (long)(n0 + r0) * K + c16 * 4;
    uint32_t sa = sA + r0 * RSTR + c16 * 16;
    uint32_t sb = sB + r0 * RSTR + c16 * 16;

#define ISSUE_STAGE(s) do { \
    long k0g = (long)(s) * 32; \
    uint32_t so = ((s) % NSTAGES) * STG; \
    _Pragma("unroll") \
    for (int i_ = 0; i_ < 8; i_++) { \
        CP_ASYNC16(sa + so + i_ * (16 * RSTR), Agp + (long)(16 * i_) * K + k0g); \
        CP_ASYNC16(sb + so + i_ * (16 * RSTR), Bgp + (long)(16 * i_) * K + k0g); \
    } \
    CP_COMMIT(); } while (0)

    int g = lane >> 3;
    int rl = lane & 7;
    uint32_t aoff = (uint32_t)(((g & 1) * 8 + rl + wm) * RSTR + (g >> 1) * 16);
    uint32_t boff = (uint32_t)(((g >> 1) * 8 + rl + wn) * RSTR + (g & 1) * 16);

    float acc[4][8][4];
#pragma unroll
    for (int i = 0; i < 4; i++)
#pragma unroll
        for (int j = 0; j < 8; j++)
#pragma unroll
            for (int c = 0; c < 4; c++) acc[i][j][c] = 0.f;

    int nIter = K >> 5;
    ISSUE_STAGE(0);
    ISSUE_STAGE(1);

    for (int it = 0; it < nIter; it++) {
        CP_WAIT1();
        __syncthreads();
        if (it + 2 < nIter) { ISSUE_STAGE(it + 2); } else { CP_COMMIT(); }

        uint32_t slot = (uint32_t)((it % NSTAGES) * STG);
        uint32_t abase = sA + slot + aoff;
        uint32_t bbase = sB + slot + boff;
#pragma unroll
        for (int ks = 0; ks < 4; ks++) {
            uint32_t af[4][4], bf[8][2];
#pragma unroll
            for (int mi = 0; mi < 4; mi++)
                LDSM_X4(af[mi][0], af[mi][1], af[mi][2], af[mi][3],
                        abase + mi * (16 * RSTR) + ks * 32);
#pragma unroll
            for (int p = 0; p < 4; p++)
                LDSM_X4(bf[2*p][0], bf[2*p][1], bf[2*p+1][0], bf[2*p+1][1],
                        bbase + p * (16 * RSTR) + ks * 32);
#pragma unroll
            for (int mi = 0; mi < 4; mi++)
#pragma unroll
                for (int ni = 0; ni < 8; ni++)
                    MMA_TF32(acc[mi][ni], af[mi], bf[ni]);
        }
    }
#undef ISSUE_STAGE

#pragma unroll
    for (int mi = 0; mi < 4; mi++) {
        long r_lo = m0 + wm + mi * 16 + (lane >> 2);
        long r_hi = r_lo + 8;
#pragma unroll
        for (int ni = 0; ni < 8; ni++) {
            int col = n0 + wn + ni * 8 + (lane & 3) * 2;
            float2 bv = *(const float2*)(bias + col);
            float v0 = acc[mi][ni][0] + bv.x;
            float v1 = acc[mi][ni][1] + bv.y;
            float v2 = acc[mi][ni][2] + bv.x;
            float v3 = acc[mi][ni][3] + bv.y;
            if (RES) {
                float2 rr0 = *(const float2*)(res + r_lo * N + col);
                float2 rr1 = *(const float2*)(res + r_hi * N + col);
                v0 += rr0.x; v1 += rr0.y; v2 += rr1.x; v3 += rr1.y;
            }
            if (GELU) {
                v0 = 0.5f * v0 * (1.0f + erff(v0 * 0.70710678118654752f));
                v1 = 0.5f * v1 * (1.0f + erff(v1 * 0.70710678118654752f));
                v2 = 0.5f * v2 * (1.0f + erff(v2 * 0.70710678118654752f));
                v3 = 0.5f * v3 * (1.0f + erff(v3 * 0.70710678118654752f));
            }
            if (RTF) {
                v0 = tf32rf(v0); v1 = tf32rf(v1); v2 = tf32rf(v2); v3 = tf32rf(v3);
            }
            *(float2*)(C + r_lo * N + col) = make_float2(v0, v1);
            *(float2*)(C + r_hi * N + col) = make_float2(v2, v3);
        }
    }
}

// ========== GEMM B: 256x128 CTA tile, 8 warps (4Mx2N), warp 64x64 ==========
// For the large-N GEMMs (qkv, w1) — halves B L2-traffic; grids stay >= 384.
#define A_STAGE (256 * RSTR)                // 36864
#define B_STAGE (128 * RSTR)                // 18432
#define GEMM_BIG_SMEM (NSTAGES * (A_STAGE + B_STAGE))   // 165888

template <bool GELU, bool RTF>
__global__ __launch_bounds__(256, 1) void gemm_big(const float* __restrict__ A,
                                                   const float* __restrict__ W,
                                                   const float* __restrict__ bias,
                                                   float* __restrict__ C,
                                                   int M, int N, int K)
{
    extern __shared__ char smem[];
    uint32_t sA = smem_u32(smem);
    uint32_t sB = sA + NSTAGES * A_STAGE;

    int tid = threadIdx.x;
    int lane = tid & 31, wid = tid >> 5;
    int m0 = blockIdx.y * 256;
    int n0 = blockIdx.x * 128;
    int wm = (wid & 3) * 64;
    int wn = (wid >> 2) * 64;

    int r0 = tid >> 3;
    int c16 = tid & 7;
    const float* Agp = A + (long)(m0 + r0) * K + c16 * 4;
    const float* Bgp = W + (long)(n0 + r0) * K + c16 * 4;
    uint32_t sa = sA + r0 * RSTR + c16 * 16;
    uint32_t sb = sB + r0 * RSTR + c16 * 16;

#define ISSUE_STAGE(s) do { \
    long k0g = (long)(s) * 32; \
    uint32_t soa = ((s) % NSTAGES) * A_STAGE; \
    uint32_t sob = ((s) % NSTAGES) * B_STAGE; \
    _Pragma("unroll") \
    for (int i_ = 0; i_ < 8; i_++) \
        CP_ASYNC16(sa + soa + i_ * (32 * RSTR), Agp + (long)(32 * i_) * K + k0g); \
    _Pragma("unroll") \
    for (int i_ = 0; i_ < 4; i_++) \
        CP_ASYNC16(sb + sob + i_ * (32 * RSTR), Bgp + (long)(32 * i_) * K + k0g); \
    CP_COMMIT(); } while (0)

    int g = lane >> 3;
    int rl = lane & 7;
    uint32_t aoff = (uint32_t)(((g & 1) * 8 + rl + wm) * RSTR + (g >> 1) * 16);
    uint32_t boff = (uint32_t)(((g >> 1) * 8 + rl + wn) * RSTR + (g & 1) * 16);

    float acc[4][8][4];
#pragma unroll
    for (int i = 0; i < 4; i++)
#pragma unroll
        for (int j = 0; j < 8; j++)
#pragma unroll
            for (int c = 0; c < 4; c++) acc[i][j][c] = 0.f;

    int nIter = K >> 5;
    ISSUE_STAGE(0);
    ISSUE_STAGE(1);

    for (int it = 0; it < nIter; it++) {
        CP_WAIT1();
        __syncthreads();
        if (it + 2 < nIter) { ISSUE_STAGE(it + 2); } else { CP_COMMIT(); }

        uint32_t abase = sA + (uint32_t)((it % NSTAGES) * A_STAGE) + aoff;
        uint32_t bbase = sB + (uint32_t)((it % NSTAGES) * B_STAGE) + boff;
#pragma unroll
        for (int ks = 0; ks < 4; ks++) {
            uint32_t af[4][4], bf[8][2];
#pragma unroll
            for (int mi = 0; mi < 4; mi++)
                LDSM_X4(af[mi][0], af[mi][1], af[mi][2], af[mi][3],
                        abase + mi * (16 * RSTR) + ks * 32);
#pragma unroll
            for (int p = 0; p < 4; p++)
                LDSM_X4(bf[2*p][0], bf[2*p][1], bf[2*p+1][0], bf[2*p+1][1],
                        bbase + p * (16 * RSTR) + ks * 32);
#pragma unroll
            for (int mi = 0; mi < 4; mi++)
#pragma unroll
                for (int ni = 0; ni < 8; ni++)
                    MMA_TF32(acc[mi][ni], af[mi], bf[ni]);
        }
    }
#undef ISSUE_STAGE

#pragma unroll
    for (int mi = 0; mi < 4; mi++) {
        long r_lo = m0 + wm + mi * 16 + (lane >> 2);
        long r_hi = r_lo + 8;
#pragma unroll
        for (int ni = 0; ni < 8; ni++) {
            int col = n0 + wn + ni * 8 + (lane & 3) * 2;
            float2 bv = *(const float2*)(bias + col);
            float v0 = acc[mi][ni][0] + bv.x;
            float v1 = acc[mi][ni][1] + bv.y;
            float v2 = acc[mi][ni][2] + bv.x;
            float v3 = acc[mi][ni][3] + bv.y;
            if (GELU) {
                v0 = 0.5f * v0 * (1.0f + erff(v0 * 0.70710678118654752f));
                v1 = 0.5f * v1 * (1.0f + erff(v1 * 0.70710678118654752f));
                v2 = 0.5f * v2 * (1.0f + erff(v2 * 0.70710678118654752f));
                v3 = 0.5f * v3 * (1.0f + erff(v3 * 0.70710678118654752f));
            }
            if (RTF) {
                v0 = tf32rf(v0); v1 = tf32rf(v1); v2 = tf32rf(v2); v3 = tf32rf(v3);
            }
            *(float2*)(C + r_lo * N + col) = make_float2(v0, v1);
            *(float2*)(C + r_hi * N + col) = make_float2(v2, v3);
        }
    }
}

// ---------------- LayerNorm (outputs tf32-rounded) ----------------
__global__ __launch_bounds__(256) void ln_kernel(const float* __restrict__ x,
                                                 const float* __restrict__ g,
                                                 const float* __restrict__ bt,
                                                 float* __restrict__ out)
{
    int row = blockIdx.x;
    const float* xr = x + (long)row * DD;
    float v[4];
    float s = 0.f, s2 = 0.f;
#pragma unroll
    for (int i = 0; i < 4; i++) {
        v[i] = xr[threadIdx.x + i * 256];
        s += v[i];
        s2 += v[i] * v[i];
    }
    int lane = threadIdx.x & 31, warp = threadIdx.x >> 5;
#pragma unroll
    for (int off = 16; off > 0; off >>= 1) {
        s  += __shfl_xor_sync(0xffffffffu, s,  off);
        s2 += __shfl_xor_sync(0xffffffffu, s2, off);
    }
    __shared__ float sm[8], sm2[8];
    if (lane == 0) { sm[warp] = s; sm2[warp] = s2; }
    __syncthreads();
    if (threadIdx.x == 0) {
        float a = 0.f, b = 0.f;
#pragma unroll
        for (int i = 0; i < 8; i++) { a += sm[i]; b += sm2[i]; }
        float mean = a * (1.0f / DD);
        float var  = b * (1.0f / DD) - mean * mean;
        sm[0] = mean;
        sm2[0] = rsqrtf(var + 1e-5f);
    }
    __syncthreads();
    float mean = sm[0], inv = sm2[0];
    float* orow = out + (long)row * DD;
#pragma unroll
    for (int i = 0; i < 4; i++) {
        int c = threadIdx.x + i * 256;
        orow[c] = tf32rf((v[i] - mean) * inv * g[c] + bt[c]);
    }
}

// ---------------- mma-tiled sparse attention (QT=32, 2 CTAs/SM) ----------------
// Keys for queries [q0, q0+31]: globals [0,16) + window [max(16,q0-128), q0+31]
// => at most 16 + 160 = 176 real keys; padded to KP=192.
#define QT 32
#define KP 192
#define QSTR 68
#define KSTR 68
#define VSTR 72
#define SSTR 196
#define ATTN_SMEM ((QT*QSTR + KP*VSTR + QT*SSTR + KP + QT) * 4)   // 89984

__global__ __launch_bounds__(256, 2) void attn_mma(const float* __restrict__ qkv,
                                                   const int* __restrict__ am,
                                                   float* __restrict__ o)
{
    extern __shared__ float sf[];
    float* sQ  = sf;
    float* sKV = sQ + QT * QSTR;
    float* sS  = sKV + KP * VSTR;
    float* sAm = sS + QT * SSTR;
    float* sDen = sAm + KP;

    uint32_t sQb  = smem_u32(sQ);
    uint32_t sKVb = smem_u32(sKV);
    uint32_t sSb  = smem_u32(sS);

    int tid = threadIdx.x;
    int lane = tid & 31, wid = tid >> 5;
    int q0 = blockIdx.x * QT;
    int h = blockIdx.y & 15;
    int b = blockIdx.y >> 4;

    int koff = max(0, q0 - WINDOW - NGLOB);
    int NK = min(KP - 16, q0 + QT);          // min(176, q0+32)

    const float* qbase = qkv + ((long)b * SS) * (3 * DD) + h * DH;

    // ---- load Q (tf32-rounded): 32 rows x 16 float4 chunks ----
#pragma unroll
    for (int t = 0; t < 2; t++) {
        int f = tid + t * 256;
        int row = f >> 4, ch = f & 15;
        float4 v = *(const float4*)(qbase + (long)(q0 + row) * (3 * DD) + ch * 4);
        v.x = tf32rf(v.x); v.y = tf32rf(v.y); v.z = tf32rf(v.z); v.w = tf32rf(v.w);
        *(float4*)(sQ + row * QSTR + ch * 4) = v;
    }
    // ---- load K: 192 rows x 16 chunks ----
#pragma unroll
    for (int t = 0; t < 12; t++) {
        int f = tid + t * 256;
        int idx = f >> 4, ch = f & 15;
        float4 v = make_float4(0.f, 0.f, 0.f, 0.f);
        if (idx < NK) {
            int key = idx + (idx < NGLOB ? 0 : koff);
            v = *(const float4*)(qbase + (long)key * (3 * DD) + DD + ch * 4);
            v.x = tf32rf(v.x); v.y = tf32rf(v.y); v.z = tf32rf(v.z); v.w = tf32rf(v.w);
        }
        *(float4*)(sKV + idx * KSTR + ch * 4) = v;
    }
    if (tid < KP) {
        int idx = tid;
        float a = NEGV;
        if (idx < NK) {
            int key = idx + (idx < NGLOB ? 0 : koff);
            a = (am[b * SS + key] == 0) ? NEGV : 0.f;
        }
        sAm[idx] = a;
    }
    __syncthreads();

    int g = lane >> 3;
    int rl = lane & 7;
    // ---- phase 1: S = Q @ K^T  (warps 2M x 4N; warp tile 16q x 48k) ----
    int wm = (wid & 1) * 16;
    int wn = (wid >> 1) * 48;
    {
        float acc[6][4];
#pragma unroll
        for (int j = 0; j < 6; j++)
#pragma unroll
            for (int c = 0; c < 4; c++) acc[j][c] = 0.f;

        uint32_t aQ = sQb + (wm + (g & 1) * 8 + rl) * (QSTR * 4) + (g >> 1) * 16;
        uint32_t bK = sKVb + (wn + (g >> 1) * 8 + rl) * (KSTR * 4) + (g & 1) * 16;
#pragma unroll
        for (int ks = 0; ks < 8; ks++) {
            uint32_t af[4], bf[6][2];
            LDSM_X4(af[0], af[1], af[2], af[3], aQ + ks * 32);
#pragma unroll
            for (int p = 0; p < 3; p++)
                LDSM_X4(bf[2*p][0], bf[2*p][1], bf[2*p+1][0], bf[2*p+1][1],
                        bK + p * (16 * KSTR * 4) + ks * 32);
#pragma unroll
            for (int nt = 0; nt < 6; nt++)
                MMA_TF32(acc[nt], af, bf[nt]);
        }

        // masked scaled store to sS
        int r0 = wm + (lane >> 2);
        int r1 = r0 + 8;
        int qa0 = q0 + r0, qa1 = q0 + r1;
#pragma unroll
        for (int nt = 0; nt < 6; nt++) {
            int col = wn + nt * 8 + 2 * (lane & 3);
#pragma unroll
            for (int cc = 0; cc < 2; cc++) {
                int cidx = col + cc;
                int key = cidx + (cidx < NGLOB ? 0 : koff);
                float amv = sAm[cidx];
                bool ok0 = (cidx < NK) && (key <= qa0) && ((key < NGLOB) || (key >= qa0 - WINDOW));
                bool ok1 = (cidx < NK) && (key <= qa1) && ((key < NGLOB) || (key >= qa1 - WINDOW));
                sS[r0 * SSTR + cidx] = ok0 ? acc[nt][cc] * 0.125f + amv : NEGV;
                sS[r1 * SSTR + cidx] = ok1 ? acc[nt][2 + cc] * 0.125f + amv : NEGV;
            }
        }
    }
    __syncthreads();

    // ---- load V (overwrites K region; stride VSTR) ----
#pragma unroll
    for (int t = 0; t < 12; t++) {
        int f = tid + t * 256;
        int idx = f >> 4, ch = f & 15;
        float4 v = make_float4(0.f, 0.f, 0.f, 0.f);
        if (idx < NK) {
            int key = idx + (idx < NGLOB ? 0 : koff);
            v = *(const float4*)(qbase + (long)key * (3 * DD) + 2 * DD + ch * 4);
            v.x = tf32rf(v.x); v.y = tf32rf(v.y); v.z = tf32rf(v.z); v.w = tf32rf(v.w);
        }
        *(float4*)(sKV + idx * VSTR + ch * 4) = v;
    }

    // ---- phase 2: softmax rows (warp w: rows w*4 .. w*4+3) ----
#pragma unroll
    for (int i = 0; i < 4; i++) {
        int r = wid * 4 + i;
        float v[6];
#pragma unroll
        for (int j = 0; j < 6; j++) v[j] = sS[r * SSTR + lane + j * 32];
        float mx = v[0];
#pragma unroll
        for (int j = 1; j < 6; j++) mx = fmaxf(mx, v[j]);
#pragma unroll
        for (int off = 16; off > 0; off >>= 1) mx = fmaxf(mx, __shfl_xor_sync(0xffffffffu, mx, off));
        float sum = 0.f;
#pragma unroll
        for (int j = 0; j < 6; j++) {
            float e = __expf(v[j] - mx);
            e = tf32rf(e);
            sum += e;
            sS[r * SSTR + lane + j * 32] = e;
        }
#pragma unroll
        for (int off = 16; off > 0; off >>= 1) sum += __shfl_xor_sync(0xffffffffu, sum, off);
        if (lane == 0) sDen[r] = sum;
    }
    __syncthreads();

    // ---- phase 3: O = P @ V  (warps 2M x 4N; warp tile 16q x 16d) ----
    {
        int wm2 = (wid & 1) * 16;
        int wn2 = (wid >> 1) * 16;
        float acc2[2][4];
#pragma unroll
        for (int j = 0; j < 2; j++)
#pragma unroll
            for (int c = 0; c < 4; c++) acc2[j][c] = 0.f;

        uint32_t aS = sSb + (wm2 + (g & 1) * 8 + rl) * (SSTR * 4) + (g >> 1) * 16;
#pragma unroll
        for (int ks = 0; ks < 24; ks++) {
            uint32_t af[4];
            LDSM_X4(af[0], af[1], af[2], af[3], aS + ks * 32);
            int k0 = ks * 8 + (lane & 3);
            int nb = wn2 + (lane >> 2);
            uint32_t bf[2][2];
#pragma unroll
            for (int nt = 0; nt < 2; nt++) {
                bf[nt][0] = __float_as_uint(sKV[k0 * VSTR + nb + nt * 8]);
                bf[nt][1] = __float_as_uint(sKV[(k0 + 4) * VSTR + nb + nt * 8]);
            }
#pragma unroll
            for (int nt = 0; nt < 2; nt++)
                MMA_TF32(acc2[nt], af, bf[nt]);
        }

        int r0o = wm2 + (lane >> 2);
        int r1o = r0o + 8;
        float inv0 = 1.f / sDen[r0o];
        float inv1 = 1.f / sDen[r1o];
        float* ob0 = o + ((long)(b * SS + q0 + r0o)) * DD + h * DH;
        float* ob1 = o + ((long)(b * SS + q0 + r1o)) * DD + h * DH;
#pragma unroll
        for (int nt = 0; nt < 2; nt++) {
            int col = wn2 + nt * 8 + 2 * (lane & 3);
            *(float2*)(ob0 + col) = make_float2(tf32rf(acc2[nt][0] * inv0), tf32rf(acc2[nt][1] * inv0));
            *(float2*)(ob1 + col) = make_float2(tf32rf(acc2[nt][2] * inv1), tf32rf(acc2[nt][3] * inv1));
        }
    }
}

// ---------------- launch ----------------
extern "C" void kernel_launch(void* const* d_in, const int* in_sizes, int n_in,
                              void* d_out, int out_size)
{
    const float* x     = (const float*)d_in[0];
    const int*   am    = (const int*)  d_in[1];
    const float* w_in  = (const float*)d_in[2];
    const float* b_in  = (const float*)d_in[3];
    const float* w_out = (const float*)d_in[4];
    const float* b_out = (const float*)d_in[5];
    const float* g1    = (const float*)d_in[6];
    const float* bl1   = (const float*)d_in[7];
    const float* g2    = (const float*)d_in[8];
    const float* bl2   = (const float*)d_in[9];
    const float* w1    = (const float*)d_in[10];
    const float* b1    = (const float*)d_in[11];
    const float* w2    = (const float*)d_in[12];
    const float* b2    = (const float*)d_in[13];
    float* out = (float*)d_out;

    void *p_hln, *p_qkv, *p_o, *p_x1, *p_h2, *p_wr;
    cudaGetSymbolAddress(&p_hln, g_hln);
    cudaGetSymbolAddress(&p_qkv, g_qkv);
    cudaGetSymbolAddress(&p_o,   g_o);
    cudaGetSymbolAddress(&p_x1,  g_x1);
    cudaGetSymbolAddress(&p_h2,  g_h2);
    cudaGetSymbolAddress(&p_wr,  g_wr);
    float* hln = (float*)p_hln;
    float* qkv = (float*)p_qkv;
    float* o   = (float*)p_o;
    float* x1  = (float*)p_x1;
    float* h2  = (float*)p_h2;
    float* wr  = (float*)p_wr;

    cudaFuncSetAttribute(gemm_mma<false, true,  false>, cudaFuncAttributeMaxDynamicSharedMemorySize, GEMM_SMEM);
    cudaFuncSetAttribute(gemm_big<false, false>, cudaFuncAttributeMaxDynamicSharedMemorySize, GEMM_BIG_SMEM);
    cudaFuncSetAttribute(gemm_big<true,  true >, cudaFuncAttributeMaxDynamicSharedMemorySize, GEMM_BIG_SMEM);
    cudaFuncSetAttribute(attn_mma, cudaFuncAttributeMaxDynamicSharedMemorySize, ATTN_SMEM);

    // 0. round weights to tf32
    wprep_kernel<<<WTOTAL / (256 * 4), 256>>>(w_in, w_out, w1, w2);
    // 1. LN1
    ln_kernel<<<ROWS, 256>>>(x, g1, bl1, hln);
    // 2. qkv = hln @ w_in^T + b_in   (big tile: grid 24x16 = 384)
    gemm_big<false, false><<<dim3(3 * DD / 128, ROWS / 256), 256, GEMM_BIG_SMEM>>>(hln, wr + OFF_WIN, b_in, qkv, ROWS, 3 * DD, DD);
    // 3. attention -> o   (QT=32: grid 64x32 = 2048, 2 CTAs/SM)
    attn_mma<<<dim3(SS / QT, BB * HH), 256, ATTN_SMEM>>>(qkv, am, o);
    // 4. x1 = x + o @ w_out^T + b_out   (grid 8x32 = 256)
    gemm_mma<false, true, false><<<dim3(DD / 128, ROWS / 128), 128, GEMM_SMEM>>>(o, wr + OFF_WOUT, b_out, x, x1, ROWS, DD, DD);
    // 5. LN2
    ln_kernel<<<ROWS, 256>>>(x1, g2, bl2, hln);
    // 6. h2 = gelu(hln @ w1^T + b1), tf32-rounded   (big tile: grid 32x16 = 512)
    gemm_big<true, true><<<dim3(FF / 128, ROWS / 256), 256, GEMM_BIG_SMEM>>>(hln, wr + OFF_W1, b1, h2, ROWS, FF, DD);
    // 7. out = x1 + h2 @ w2^T + b2   (grid 8x32 = 256)
    gemm_mma<false, true, false><<<dim3(DD / 128, ROWS / 128), 128, GEMM_SMEM>>>(h2, wr + OFF_W2, b2, x1, out, ROWS, DD, FF);
}

// round 11
// speedup vs baseline: 1.0476x; 1.0476x over previous
#include <cuda_runtime.h>
#include <math.h>
#include <cstdint>

// Problem constants
#define BB 2
#define SS 2048
#define DD 1024
#define HH 16
#define DH 64
#define FF 4096
#define ROWS (BB*SS)          // 4096
#define WINDOW 128
#define NGLOB 16
#define NEGV -1e9f

// weight offsets inside g_wr
#define OFF_WIN  0
#define OFF_WOUT (3*DD*DD)
#define OFF_W1   (OFF_WOUT + DD*DD)
#define OFF_W2   (OFF_W1 + FF*DD)
#define WTOTAL   (OFF_W2 + DD*FF)

// ---------------- scratch ----------------
__device__ float g_hln[ROWS * DD];
__device__ float g_qkv[ROWS * 3 * DD];
__device__ float g_o  [ROWS * DD];
__device__ float g_x1 [ROWS * DD];
__device__ float g_h2 [ROWS * FF];
__device__ float g_wr [WTOTAL];

// ---------------- helpers ----------------
__device__ __forceinline__ float tf32rf(float f) {
    uint32_t u;
    asm("cvt.rna.tf32.f32 %0, %1;" : "=r"(u) : "f"(f));
    return __uint_as_float(u);
}
__device__ __forceinline__ uint32_t smem_u32(const void* p) {
    uint32_t a;
    asm("{ .reg .u64 t; cvta.to.shared.u64 t, %1; cvt.u32.u64 %0, t; }" : "=r"(a) : "l"(p));
    return a;
}
#define CP_ASYNC16(sdst, gsrc) \
    asm volatile("cp.async.cg.shared.global [%0], [%1], 16;" :: "r"(sdst), "l"(gsrc))
#define CP_COMMIT() asm volatile("cp.async.commit_group;" ::: "memory")
#define CP_WAIT1()  asm volatile("cp.async.wait_group 1;" ::: "memory")

#define LDSM_X4(r0, r1, r2, r3, addr) \
    asm volatile("ldmatrix.sync.aligned.m8n8.x4.shared.b16 {%0,%1,%2,%3}, [%4];" \
        : "=r"(r0), "=r"(r1), "=r"(r2), "=r"(r3) : "r"(addr))

#define MMA_TF32(c, a, b) \
    asm volatile("mma.sync.aligned.m16n8k8.row.col.f32.tf32.tf32.f32 " \
        "{%0,%1,%2,%3}, {%4,%5,%6,%7}, {%8,%9}, {%0,%1,%2,%3};" \
        : "+f"((c)[0]), "+f"((c)[1]), "+f"((c)[2]), "+f"((c)[3]) \
        : "r"((a)[0]), "r"((a)[1]), "r"((a)[2]), "r"((a)[3]), \
          "r"((b)[0]), "r"((b)[1]))

// ---------------- weight tf32 pre-round ----------------
__global__ __launch_bounds__(256) void wprep_kernel(const float* __restrict__ w_in,
                                                    const float* __restrict__ w_out,
                                                    const float* __restrict__ w1,
                                                    const float* __restrict__ w2)
{
    long i = ((long)blockIdx.x * 256 + threadIdx.x) * 4;
    float4 v;
    if (i < OFF_WOUT)      v = *(const float4*)(w_in + i);
    else if (i < OFF_W1)   v = *(const float4*)(w_out + (i - OFF_WOUT));
    else if (i < OFF_W2)   v = *(const float4*)(w1 + (i - OFF_W1));
    else                   v = *(const float4*)(w2 + (i - OFF_W2));
    v.x = tf32rf(v.x); v.y = tf32rf(v.y); v.z = tf32rf(v.z); v.w = tf32rf(v.w);
    *(float4*)(g_wr + i) = v;
}

// ---------------- tf32 mma.sync GEMM (R6 config: best measured) ----------------
// CTA tile 128x128, BK=32, 3-stage cp.async, 8 warps (2M x 4N), warp tile 64x32.
#define RSTR 144                            // smem row stride bytes (36 floats)
#define STG  (128 * RSTR)                   // 18432 per matrix per stage
#define NSTAGES 3
#define GEMM_SMEM (2 * NSTAGES * STG)       // 110592

template <bool GELU, bool RES, bool RTF>
__global__ __launch_bounds__(256, 2) void gemm_mma(const float* __restrict__ A,
                                                   const float* __restrict__ W,
                                                   const float* __restrict__ bias,
                                                   const float* __restrict__ res,
                                                   float* __restrict__ C,
                                                   int M, int N, int K)
{
    extern __shared__ char smem[];
    uint32_t sA = smem_u32(smem);
    uint32_t sB = sA + NSTAGES * STG;

    int tid = threadIdx.x;
    int lane = tid & 31, wid = tid >> 5;
    int m0 = blockIdx.y * 128;
    int n0 = blockIdx.x * 128;
    int wm = (wid & 1) * 64;
    int wn = (wid >> 1) * 32;

    int r0 = tid >> 3;                 // 0..31
    int c16 = tid & 7;                 // 0..7
    const float* Agp = A + (long)(m0 + r0) * K + c16 * 4;
    const float* Bgp = W + (long)(n0 + r0) * K + c16 * 4;
    uint32_t sa = sA + r0 * RSTR + c16 * 16;
    uint32_t sb = sB + r0 * RSTR + c16 * 16;

#define ISSUE_STAGE(s) do { \
    long k0g = (long)(s) * 32; \
    uint32_t so = ((s) % NSTAGES) * STG; \
    _Pragma("unroll") \
    for (int i_ = 0; i_ < 4; i_++) { \
        CP_ASYNC16(sa + so + i_ * (32 * RSTR), Agp + (long)(32 * i_) * K + k0g); \
        CP_ASYNC16(sb + so + i_ * (32 * RSTR), Bgp + (long)(32 * i_) * K + k0g); \
    } \
    CP_COMMIT(); } while (0)

    int g = lane >> 3;
    int rl = lane & 7;
    uint32_t aoff = (uint32_t)(((g & 1) * 8 + rl + wm) * RSTR + (g >> 1) * 16);
    uint32_t boff = (uint32_t)(((g >> 1) * 8 + rl + wn) * RSTR + (g & 1) * 16);

    float acc[4][4][4];
#pragma unroll
    for (int i = 0; i < 4; i++)
#pragma unroll
        for (int j = 0; j < 4; j++)
#pragma unroll
            for (int c = 0; c < 4; c++) acc[i][j][c] = 0.f;

    int nIter = K >> 5;
    ISSUE_STAGE(0);
    ISSUE_STAGE(1);

    for (int it = 0; it < nIter; it++) {
        CP_WAIT1();
        __syncthreads();
        if (it + 2 < nIter) { ISSUE_STAGE(it + 2); } else { CP_COMMIT(); }

        uint32_t slot = (uint32_t)((it % NSTAGES) * STG);
        uint32_t abase = sA + slot + aoff;
        uint32_t bbase = sB + slot + boff;
#pragma unroll
        for (int ks = 0; ks < 4; ks++) {
            uint32_t af[4][4], bf[4][2];
#pragma unroll
            for (int mi = 0; mi < 4; mi++)
                LDSM_X4(af[mi][0], af[mi][1], af[mi][2], af[mi][3],
                        abase + mi * (16 * RSTR) + ks * 32);
#pragma unroll
            for (int p = 0; p < 2; p++)
                LDSM_X4(bf[2*p][0], bf[2*p][1], bf[2*p+1][0], bf[2*p+1][1],
                        bbase + p * (16 * RSTR) + ks * 32);
#pragma unroll
            for (int mi = 0; mi < 4; mi++)
#pragma unroll
                for (int ni = 0; ni < 4; ni++)
                    MMA_TF32(acc[mi][ni], af[mi], bf[ni]);
        }
    }
#undef ISSUE_STAGE

#pragma unroll
    for (int mi = 0; mi < 4; mi++) {
        long r_lo = m0 + wm + mi * 16 + (lane >> 2);
        long r_hi = r_lo + 8;
#pragma unroll
        for (int ni = 0; ni < 4; ni++) {
            int col = n0 + wn + ni * 8 + (lane & 3) * 2;
            float2 bv = *(const float2*)(bias + col);
            float v0 = acc[mi][ni][0] + bv.x;
            float v1 = acc[mi][ni][1] + bv.y;
            float v2 = acc[mi][ni][2] + bv.x;
            float v3 = acc[mi][ni][3] + bv.y;
            if (RES) {
                float2 rr0 = *(const float2*)(res + r_lo * N + col);
                float2 rr1 = *(const float2*)(res + r_hi * N + col);
                v0 += rr0.x; v1 += rr0.y; v2 += rr1.x; v3 += rr1.y;
            }
            if (GELU) {
                v0 = 0.5f * v0 * (1.0f + erff(v0 * 0.70710678118654752f));
                v1 = 0.5f * v1 * (1.0f + erff(v1 * 0.70710678118654752f));
                v2 = 0.5f * v2 * (1.0f + erff(v2 * 0.70710678118654752f));
                v3 = 0.5f * v3 * (1.0f + erff(v3 * 0.70710678118654752f));
            }
            if (RTF) {
                v0 = tf32rf(v0); v1 = tf32rf(v1); v2 = tf32rf(v2); v3 = tf32rf(v3);
            }
            *(float2*)(C + r_lo * N + col) = make_float2(v0, v1);
            *(float2*)(C + r_hi * N + col) = make_float2(v2, v3);
        }
    }
}

// ---------------- LayerNorm (outputs tf32-rounded) ----------------
__global__ __launch_bounds__(256) void ln_kernel(const float* __restrict__ x,
                                                 const float* __restrict__ g,
                                                 const float* __restrict__ bt,
                                                 float* __restrict__ out)
{
    int row = blockIdx.x;
    const float* xr = x + (long)row * DD;
    float v[4];
    float s = 0.f, s2 = 0.f;
#pragma unroll
    for (int i = 0; i < 4; i++) {
        v[i] = xr[threadIdx.x + i * 256];
        s += v[i];
        s2 += v[i] * v[i];
    }
    int lane = threadIdx.x & 31, warp = threadIdx.x >> 5;
#pragma unroll
    for (int off = 16; off > 0; off >>= 1) {
        s  += __shfl_xor_sync(0xffffffffu, s,  off);
        s2 += __shfl_xor_sync(0xffffffffu, s2, off);
    }
    __shared__ float sm[8], sm2[8];
    if (lane == 0) { sm[warp] = s; sm2[warp] = s2; }
    __syncthreads();
    if (threadIdx.x == 0) {
        float a = 0.f, b = 0.f;
#pragma unroll
        for (int i = 0; i < 8; i++) { a += sm[i]; b += sm2[i]; }
        float mean = a * (1.0f / DD);
        float var  = b * (1.0f / DD) - mean * mean;
        sm[0] = mean;
        sm2[0] = rsqrtf(var + 1e-5f);
    }
    __syncthreads();
    float mean = sm[0], inv = sm2[0];
    float* orow = out + (long)row * DD;
#pragma unroll
    for (int i = 0; i < 4; i++) {
        int c = threadIdx.x + i * 256;
        orow[c] = tf32rf((v[i] - mean) * inv * g[c] + bt[c]);
    }
}

// ---------------- mma-tiled sparse attention (QT=32, 2 CTAs/SM — R10 win) ----------------
#define QT 32
#define KP 192
#define QSTR 68
#define KSTR 68
#define VSTR 72
#define SSTR 196
#define ATTN_SMEM ((QT*QSTR + KP*VSTR + QT*SSTR + KP + QT) * 4)   // 89984

__global__ __launch_bounds__(256, 2) void attn_mma(const float* __restrict__ qkv,
                                                   const int* __restrict__ am,
                                                   float* __restrict__ o)
{
    extern __shared__ float sf[];
    float* sQ  = sf;
    float* sKV = sQ + QT * QSTR;
    float* sS  = sKV + KP * VSTR;
    float* sAm = sS + QT * SSTR;
    float* sDen = sAm + KP;

    uint32_t sQb  = smem_u32(sQ);
    uint32_t sKVb = smem_u32(sKV);
    uint32_t sSb  = smem_u32(sS);

    int tid = threadIdx.x;
    int lane = tid & 31, wid = tid >> 5;
    int q0 = blockIdx.x * QT;
    int h = blockIdx.y & 15;
    int b = blockIdx.y >> 4;

    int koff = max(0, q0 - WINDOW - NGLOB);
    int NK = min(KP - 16, q0 + QT);          // min(176, q0+32)

    const float* qbase = qkv + ((long)b * SS) * (3 * DD) + h * DH;

#pragma unroll
    for (int t = 0; t < 2; t++) {
        int f = tid + t * 256;
        int row = f >> 4, ch = f & 15;
        float4 v = *(const float4*)(qbase + (long)(q0 + row) * (3 * DD) + ch * 4);
        v.x = tf32rf(v.x); v.y = tf32rf(v.y); v.z = tf32rf(v.z); v.w = tf32rf(v.w);
        *(float4*)(sQ + row * QSTR + ch * 4) = v;
    }
#pragma unroll
    for (int t = 0; t < 12; t++) {
        int f = tid + t * 256;
        int idx = f >> 4, ch = f & 15;
        float4 v = make_float4(0.f, 0.f, 0.f, 0.f);
        if (idx < NK) {
            int key = idx + (idx < NGLOB ? 0 : koff);
            v = *(const float4*)(qbase + (long)key * (3 * DD) + DD + ch * 4);
            v.x = tf32rf(v.x); v.y = tf32rf(v.y); v.z = tf32rf(v.z); v.w = tf32rf(v.w);
        }
        *(float4*)(sKV + idx * KSTR + ch * 4) = v;
    }
    if (tid < KP) {
        int idx = tid;
        float a = NEGV;
        if (idx < NK) {
            int key = idx + (idx < NGLOB ? 0 : koff);
            a = (am[b * SS + key] == 0) ? NEGV : 0.f;
        }
        sAm[idx] = a;
    }
    __syncthreads();

    int g = lane >> 3;
    int rl = lane & 7;
    // ---- phase 1: S = Q @ K^T  (warps 2M x 4N; warp tile 16q x 48k) ----
    int wm = (wid & 1) * 16;
    int wn = (wid >> 1) * 48;
    {
        float acc[6][4];
#pragma unroll
        for (int j = 0; j < 6; j++)
#pragma unroll
            for (int c = 0; c < 4; c++) acc[j][c] = 0.f;

        uint32_t aQ = sQb + (wm + (g & 1) * 8 + rl) * (QSTR * 4) + (g >> 1) * 16;
        uint32_t bK = sKVb + (wn + (g >> 1) * 8 + rl) * (KSTR * 4) + (g & 1) * 16;
#pragma unroll
        for (int ks = 0; ks < 8; ks++) {
            uint32_t af[4], bf[6][2];
            LDSM_X4(af[0], af[1], af[2], af[3], aQ + ks * 32);
#pragma unroll
            for (int p = 0; p < 3; p++)
                LDSM_X4(bf[2*p][0], bf[2*p][1], bf[2*p+1][0], bf[2*p+1][1],
                        bK + p * (16 * KSTR * 4) + ks * 32);
#pragma unroll
            for (int nt = 0; nt < 6; nt++)
                MMA_TF32(acc[nt], af, bf[nt]);
        }

        int r0 = wm + (lane >> 2);
        int r1 = r0 + 8;
        int qa0 = q0 + r0, qa1 = q0 + r1;
#pragma unroll
        for (int nt = 0; nt < 6; nt++) {
            int col = wn + nt * 8 + 2 * (lane & 3);
#pragma unroll
            for (int cc = 0; cc < 2; cc++) {
                int cidx = col + cc;
                int key = cidx + (cidx < NGLOB ? 0 : koff);
                float amv = sAm[cidx];
                bool ok0 = (cidx < NK) && (key <= qa0) && ((key < NGLOB) || (key >= qa0 - WINDOW));
                bool ok1 = (cidx < NK) && (key <= qa1) && ((key < NGLOB) || (key >= qa1 - WINDOW));
                sS[r0 * SSTR + cidx] = ok0 ? acc[nt][cc] * 0.125f + amv : NEGV;
                sS[r1 * SSTR + cidx] = ok1 ? acc[nt][2 + cc] * 0.125f + amv : NEGV;
            }
        }
    }
    __syncthreads();

#pragma unroll
    for (int t = 0; t < 12; t++) {
        int f = tid + t * 256;
        int idx = f >> 4, ch = f & 15;
        float4 v = make_float4(0.f, 0.f, 0.f, 0.f);
        if (idx < NK) {
            int key = idx + (idx < NGLOB ? 0 : koff);
            v = *(const float4*)(qbase + (long)key * (3 * DD) + 2 * DD + ch * 4);
            v.x = tf32rf(v.x); v.y = tf32rf(v.y); v.z = tf32rf(v.z); v.w = tf32rf(v.w);
        }
        *(float4*)(sKV + idx * VSTR + ch * 4) = v;
    }

#pragma unroll
    for (int i = 0; i < 4; i++) {
        int r = wid * 4 + i;
        float v[6];
#pragma unroll
        for (int j = 0; j < 6; j++) v[j] = sS[r * SSTR + lane + j * 32];
        float mx = v[0];
#pragma unroll
        for (int j = 1; j < 6; j++) mx = fmaxf(mx, v[j]);
#pragma unroll
        for (int off = 16; off > 0; off >>= 1) mx = fmaxf(mx, __shfl_xor_sync(0xffffffffu, mx, off));
        float sum = 0.f;
#pragma unroll
        for (int j = 0; j < 6; j++) {
            float e = __expf(v[j] - mx);
            e = tf32rf(e);
            sum += e;
            sS[r * SSTR + lane + j * 32] = e;
        }
#pragma unroll
        for (int off = 16; off > 0; off >>= 1) sum += __shfl_xor_sync(0xffffffffu, sum, off);
        if (lane == 0) sDen[r] = sum;
    }
    __syncthreads();

    {
        int wm2 = (wid & 1) * 16;
        int wn2 = (wid >> 1) * 16;
        float acc2[2][4];
#pragma unroll
        for (int j = 0; j < 2; j++)
#pragma unroll
            for (int c = 0; c < 4; c++) acc2[j][c] = 0.f;

        uint32_t aS = sSb + (wm2 + (g & 1) * 8 + rl) * (SSTR * 4) + (g >> 1) * 16;
#pragma unroll
        for (int ks = 0; ks < 24; ks++) {
            uint32_t af[4];
            LDSM_X4(af[0], af[1], af[2], af[3], aS + ks * 32);
            int k0 = ks * 8 + (lane & 3);
            int nb = wn2 + (lane >> 2);
            uint32_t bf[2][2];
#pragma unroll
            for (int nt = 0; nt < 2; nt++) {
                bf[nt][0] = __float_as_uint(sKV[k0 * VSTR + nb + nt * 8]);
                bf[nt][1] = __float_as_uint(sKV[(k0 + 4) * VSTR + nb + nt * 8]);
            }
#pragma unroll
            for (int nt = 0; nt < 2; nt++)
                MMA_TF32(acc2[nt], af, bf[nt]);
        }

        int r0o = wm2 + (lane >> 2);
        int r1o = r0o + 8;
        float inv0 = 1.f / sDen[r0o];
        float inv1 = 1.f / sDen[r1o];
        float* ob0 = o + ((long)(b * SS + q0 + r0o)) * DD + h * DH;
        float* ob1 = o + ((long)(b * SS + q0 + r1o)) * DD + h * DH;
#pragma unroll
        for (int nt = 0; nt < 2; nt++) {
            int col = wn2 + nt * 8 + 2 * (lane & 3);
            *(float2*)(ob0 + col) = make_float2(tf32rf(acc2[nt][0] * inv0), tf32rf(acc2[nt][1] * inv0));
            *(float2*)(ob1 + col) = make_float2(tf32rf(acc2[nt][2] * inv1), tf32rf(acc2[nt][3] * inv1));
        }
    }
}

// ---------------- launch ----------------
extern "C" void kernel_launch(void* const* d_in, const int* in_sizes, int n_in,
                              void* d_out, int out_size)
{
    const float* x     = (const float*)d_in[0];
    const int*   am    = (const int*)  d_in[1];
    const float* w_in  = (const float*)d_in[2];
    const float* b_in  = (const float*)d_in[3];
    const float* w_out = (const float*)d_in[4];
    const float* b_out = (const float*)d_in[5];
    const float* g1    = (const float*)d_in[6];
    const float* bl1   = (const float*)d_in[7];
    const float* g2    = (const float*)d_in[8];
    const float* bl2   = (const float*)d_in[9];
    const float* w1    = (const float*)d_in[10];
    const float* b1    = (const float*)d_in[11];
    const float* w2    = (const float*)d_in[12];
    const float* b2    = (const float*)d_in[13];
    float* out = (float*)d_out;

    void *p_hln, *p_qkv, *p_o, *p_x1, *p_h2, *p_wr;
    cudaGetSymbolAddress(&p_hln, g_hln);
    cudaGetSymbolAddress(&p_qkv, g_qkv);
    cudaGetSymbolAddress(&p_o,   g_o);
    cudaGetSymbolAddress(&p_x1,  g_x1);
    cudaGetSymbolAddress(&p_h2,  g_h2);
    cudaGetSymbolAddress(&p_wr,  g_wr);
    float* hln = (float*)p_hln;
    float* qkv = (float*)p_qkv;
    float* o   = (float*)p_o;
    float* x1  = (float*)p_x1;
    float* h2  = (float*)p_h2;
    float* wr  = (float*)p_wr;

    cudaFuncSetAttribute(gemm_mma<false, false, false>, cudaFuncAttributeMaxDynamicSharedMemorySize, GEMM_SMEM);
    cudaFuncSetAttribute(gemm_mma<false, true,  false>, cudaFuncAttributeMaxDynamicSharedMemorySize, GEMM_SMEM);
    cudaFuncSetAttribute(gemm_mma<true,  false, true >, cudaFuncAttributeMaxDynamicSharedMemorySize, GEMM_SMEM);
    cudaFuncSetAttribute(attn_mma, cudaFuncAttributeMaxDynamicSharedMemorySize, ATTN_SMEM);

    // 0. round weights to tf32
    wprep_kernel<<<WTOTAL / (256 * 4), 256>>>(w_in, w_out, w1, w2);
    // 1. LN1
    ln_kernel<<<ROWS, 256>>>(x, g1, bl1, hln);
    // 2. qkv = hln @ w_in^T + b_in   (grid 24x32 = 768)
    gemm_mma<false, false, false><<<dim3(3 * DD / 128, ROWS / 128), 256, GEMM_SMEM>>>(hln, wr + OFF_WIN, b_in, nullptr, qkv, ROWS, 3 * DD, DD);
    // 3. attention -> o   (QT=32: grid 64x32 = 2048, 2 CTAs/SM)
    attn_mma<<<dim3(SS / QT, BB * HH), 256, ATTN_SMEM>>>(qkv, am, o);
    // 4. x1 = x + o @ w_out^T + b_out   (grid 8x32 = 256)
    gemm_mma<false, true, false><<<dim3(DD / 128, ROWS / 128), 256, GEMM_SMEM>>>(o, wr + OFF_WOUT, b_out, x, x1, ROWS, DD, DD);
    // 5. LN2
    ln_kernel<<<ROWS, 256>>>(x1, g2, bl2, hln);
    // 6. h2 = gelu(hln @ w1^T + b1), tf32-rounded   (grid 32x32 = 1024)
    gemm_mma<true, false, true><<<dim3(FF / 128, ROWS / 128), 256, GEMM_SMEM>>>(hln, wr + OFF_W1, b1, nullptr, h2, ROWS, FF, DD);
    // 7. out = x1 + h2 @ w2^T + b2   (grid 8x32 = 256)
    gemm_mma<false, true, false><<<dim3(DD / 128, ROWS / 128), 256, GEMM_SMEM>>>(h2, wr + OFF_W2, b2, x1, out, ROWS, DD, FF);
}

// round 13
// speedup vs baseline: 1.7373x; 1.6583x over previous
#include <cuda_runtime.h>
#include <cuda_fp16.h>
#include <math.h>
#include <cstdint>

// Problem constants
#define BB 2
#define SS 2048
#define DD 1024
#define HH 16
#define DH 64
#define FF 4096
#define ROWS (BB*SS)          // 4096
#define WINDOW 128
#define NGLOB 16
#define NEGV -1e9f

// input-ordered offsets inside g_wh (all weights fp16)
#define OFF_WIN  0
#define OFF_WOUT (3*DD*DD)
#define OFF_W1   (OFF_WOUT + DD*DD)
#define OFF_W2   (OFF_W1 + FF*DD)
#define WTOTAL   (OFF_W2 + DD*FF)

// ---------------- scratch ----------------
__device__ __half g_hln[ROWS * DD];         // LN outputs (fp16)
__device__ float  g_qkv[ROWS * 3 * DD];     // attention input (fp32)
__device__ __half g_o  [ROWS * DD];         // attention output (fp16)
__device__ float  g_x1 [ROWS * DD];         // x + attn residual (fp32)
__device__ __half g_h2 [ROWS * FF];         // gelu hidden (fp16)
__device__ __half g_wh [WTOTAL];            // fp16 weights

// ---------------- helpers ----------------
__device__ __forceinline__ float tf32rf(float f) {
    uint32_t u;
    asm("cvt.rna.tf32.f32 %0, %1;" : "=r"(u) : "f"(f));
    return __uint_as_float(u);
}
__device__ __forceinline__ uint32_t smem_u32(const void* p) {
    uint32_t a;
    asm("{ .reg .u64 t; cvta.to.shared.u64 t, %1; cvt.u32.u64 %0, t; }" : "=r"(a) : "l"(p));
    return a;
}
#define CP_ASYNC16(sdst, gsrc) \
    asm volatile("cp.async.cg.shared.global [%0], [%1], 16;" :: "r"(sdst), "l"(gsrc))
#define CP_COMMIT() asm volatile("cp.async.commit_group;" ::: "memory")
#define CP_WAIT1()  asm volatile("cp.async.wait_group 1;" ::: "memory")

#define LDSM_X4(r0, r1, r2, r3, addr) \
    asm volatile("ldmatrix.sync.aligned.m8n8.x4.shared.b16 {%0,%1,%2,%3}, [%4];" \
        : "=r"(r0), "=r"(r1), "=r"(r2), "=r"(r3) : "r"(addr))

#define MMA_TF32(c, a, b) \
    asm volatile("mma.sync.aligned.m16n8k8.row.col.f32.tf32.tf32.f32 " \
        "{%0,%1,%2,%3}, {%4,%5,%6,%7}, {%8,%9}, {%0,%1,%2,%3};" \
        : "+f"((c)[0]), "+f"((c)[1]), "+f"((c)[2]), "+f"((c)[3]) \
        : "r"((a)[0]), "r"((a)[1]), "r"((a)[2]), "r"((a)[3]), \
          "r"((b)[0]), "r"((b)[1]))

#define MMA_F16(c, a, b) \
    asm volatile("mma.sync.aligned.m16n8k16.row.col.f32.f16.f16.f32 " \
        "{%0,%1,%2,%3}, {%4,%5,%6,%7}, {%8,%9}, {%0,%1,%2,%3};" \
        : "+f"((c)[0]), "+f"((c)[1]), "+f"((c)[2]), "+f"((c)[3]) \
        : "r"((a)[0]), "r"((a)[1]), "r"((a)[2]), "r"((a)[3]), \
          "r"((b)[0]), "r"((b)[1]))

// ---------------- weight prep: all four -> fp16 ----------------
__global__ __launch_bounds__(256) void wprep_kernel(const float* __restrict__ w_in,
                                                    const float* __restrict__ w_out,
                                                    const float* __restrict__ w1,
                                                    const float* __restrict__ w2)
{
    long i = ((long)blockIdx.x * 256 + threadIdx.x) * 4;
    float4 v;
    if (i < OFF_WOUT)      v = *(const float4*)(w_in + i);
    else if (i < OFF_W1)   v = *(const float4*)(w_out + (i - OFF_WOUT));
    else if (i < OFF_W2)   v = *(const float4*)(w1 + (i - OFF_W1));
    else                   v = *(const float4*)(w2 + (i - OFF_W2));
    __half2 p0 = __floats2half2_rn(v.x, v.y);
    __half2 p1 = __floats2half2_rn(v.z, v.w);
    uint2 pk = make_uint2(*(uint32_t*)&p0, *(uint32_t*)&p1);
    *(uint2*)(g_wh + i) = pk;
}

#define RSTR 144                            // smem row stride bytes
#define STG  (128 * RSTR)                   // 18432 per matrix per stage
#define NSTAGES 3
#define GEMM_SMEM (2 * NSTAGES * STG)       // 110592

// ---------------- fp16 GEMM: CTA 128x128, BK=64 halves, 8 warps 2Mx4N ----------------
// C[M,N] = A[M,K] @ W[N,K]^T + bias (+res fp32) (+gelu); OUTH: fp16 out else fp32.
template <bool GELU, bool RES, bool OUTH>
__global__ __launch_bounds__(256, 2) void gemm_h(const __half* __restrict__ A,
                                                 const __half* __restrict__ W,
                                                 const float* __restrict__ bias,
                                                 const float* __restrict__ res,
                                                 void* __restrict__ Cv,
                                                 int M, int N, int K)
{
    extern __shared__ char smem[];
    uint32_t sA = smem_u32(smem);
    uint32_t sB = sA + NSTAGES * STG;

    int tid = threadIdx.x;
    int lane = tid & 31, wid = tid >> 5;
    int m0 = blockIdx.y * 128;
    int n0 = blockIdx.x * 128;
    int wm = (wid & 1) * 64;
    int wn = (wid >> 1) * 32;

    int r0 = tid >> 3;                 // 0..31
    int c16 = tid & 7;                 // 16B chunk within 128B row
    const __half* Agp = A + (long)(m0 + r0) * K + c16 * 8;
    const __half* Bgp = W + (long)(n0 + r0) * K + c16 * 8;
    uint32_t sa = sA + r0 * RSTR + c16 * 16;
    uint32_t sb = sB + r0 * RSTR + c16 * 16;

#define ISSUE_STAGE(s) do { \
    long k0g = (long)(s) * 64; \
    uint32_t so = ((s) % NSTAGES) * STG; \
    _Pragma("unroll") \
    for (int i_ = 0; i_ < 4; i_++) { \
        CP_ASYNC16(sa + so + i_ * (32 * RSTR), Agp + (long)(32 * i_) * K + k0g); \
        CP_ASYNC16(sb + so + i_ * (32 * RSTR), Bgp + (long)(32 * i_) * K + k0g); \
    } \
    CP_COMMIT(); } while (0)

    int g = lane >> 3;
    int rl = lane & 7;
    uint32_t aoff = (uint32_t)(((g & 1) * 8 + rl + wm) * RSTR + (g >> 1) * 16);
    uint32_t boff = (uint32_t)(((g >> 1) * 8 + rl + wn) * RSTR + (g & 1) * 16);

    float acc[4][4][4];
#pragma unroll
    for (int i = 0; i < 4; i++)
#pragma unroll
        for (int j = 0; j < 4; j++)
#pragma unroll
            for (int c = 0; c < 4; c++) acc[i][j][c] = 0.f;

    int nIter = K >> 6;                // BK = 64 halves
    ISSUE_STAGE(0);
    ISSUE_STAGE(1);

    for (int it = 0; it < nIter; it++) {
        CP_WAIT1();
        __syncthreads();
        if (it + 2 < nIter) { ISSUE_STAGE(it + 2); } else { CP_COMMIT(); }

        uint32_t slot = (uint32_t)((it % NSTAGES) * STG);
        uint32_t abase = sA + slot + aoff;
        uint32_t bbase = sB + slot + boff;
#pragma unroll
        for (int ks = 0; ks < 4; ks++) {   // 4 x k16
            uint32_t af[4][4], bf[4][2];
#pragma unroll
            for (int mi = 0; mi < 4; mi++)
                LDSM_X4(af[mi][0], af[mi][1], af[mi][2], af[mi][3],
                        abase + mi * (16 * RSTR) + ks * 32);
#pragma unroll
            for (int p = 0; p < 2; p++)
                LDSM_X4(bf[2*p][0], bf[2*p][1], bf[2*p+1][0], bf[2*p+1][1],
                        bbase + p * (16 * RSTR) + ks * 32);
#pragma unroll
            for (int mi = 0; mi < 4; mi++)
#pragma unroll
                for (int ni = 0; ni < 4; ni++)
                    MMA_F16(acc[mi][ni], af[mi], bf[ni]);
        }
    }
#undef ISSUE_STAGE

#pragma unroll
    for (int mi = 0; mi < 4; mi++) {
        long r_lo = m0 + wm + mi * 16 + (lane >> 2);
        long r_hi = r_lo + 8;
#pragma unroll
        for (int ni = 0; ni < 4; ni++) {
            int col = n0 + wn + ni * 8 + (lane & 3) * 2;
            float2 bv = *(const float2*)(bias + col);
            float v0 = acc[mi][ni][0] + bv.x;
            float v1 = acc[mi][ni][1] + bv.y;
            float v2 = acc[mi][ni][2] + bv.x;
            float v3 = acc[mi][ni][3] + bv.y;
            if (RES) {
                float2 rr0 = *(const float2*)(res + r_lo * N + col);
                float2 rr1 = *(const float2*)(res + r_hi * N + col);
                v0 += rr0.x; v1 += rr0.y; v2 += rr1.x; v3 += rr1.y;
            }
            if (GELU) {
                v0 = 0.5f * v0 * (1.0f + erff(v0 * 0.70710678118654752f));
                v1 = 0.5f * v1 * (1.0f + erff(v1 * 0.70710678118654752f));
                v2 = 0.5f * v2 * (1.0f + erff(v2 * 0.70710678118654752f));
                v3 = 0.5f * v3 * (1.0f + erff(v3 * 0.70710678118654752f));
            }
            if (OUTH) {
                __half* C = (__half*)Cv;
                __half2 h0 = __floats2half2_rn(v0, v1);
                __half2 h1 = __floats2half2_rn(v2, v3);
                *(__half2*)(C + r_lo * N + col) = h0;
                *(__half2*)(C + r_hi * N + col) = h1;
            } else {
                float* C = (float*)Cv;
                *(float2*)(C + r_lo * N + col) = make_float2(v0, v1);
                *(float2*)(C + r_hi * N + col) = make_float2(v2, v3);
            }
        }
    }
}

// ---------------- LayerNorm (fp32 in, fp16 out) ----------------
__global__ __launch_bounds__(256) void ln_kernel(const float* __restrict__ x,
                                                 const float* __restrict__ g,
                                                 const float* __restrict__ bt,
                                                 __half* __restrict__ out)
{
    int row = blockIdx.x;
    const float* xr = x + (long)row * DD;
    float v[4];
    float s = 0.f, s2 = 0.f;
#pragma unroll
    for (int i = 0; i < 4; i++) {
        v[i] = xr[threadIdx.x + i * 256];
        s += v[i];
        s2 += v[i] * v[i];
    }
    int lane = threadIdx.x & 31, warp = threadIdx.x >> 5;
#pragma unroll
    for (int off = 16; off > 0; off >>= 1) {
        s  += __shfl_xor_sync(0xffffffffu, s,  off);
        s2 += __shfl_xor_sync(0xffffffffu, s2, off);
    }
    __shared__ float sm[8], sm2[8];
    if (lane == 0) { sm[warp] = s; sm2[warp] = s2; }
    __syncthreads();
    if (threadIdx.x == 0) {
        float a = 0.f, b = 0.f;
#pragma unroll
        for (int i = 0; i < 8; i++) { a += sm[i]; b += sm2[i]; }
        float mean = a * (1.0f / DD);
        float var  = b * (1.0f / DD) - mean * mean;
        sm[0] = mean;
        sm2[0] = rsqrtf(var + 1e-5f);
    }
    __syncthreads();
    float mean = sm[0], inv = sm2[0];
    __half* orow = out + (long)row * DD;
#pragma unroll
    for (int i = 0; i < 4; i++) {
        int c = threadIdx.x + i * 256;
        orow[c] = __float2half((v[i] - mean) * inv * g[c] + bt[c]);
    }
}

// ---------------- mma-tiled sparse attention (QT=32, 2 CTAs/SM; fp16 output) ----------------
#define QT 32
#define KP 192
#define QSTR 68
#define KSTR 68
#define VSTR 72
#define SSTR 196
#define ATTN_SMEM ((QT*QSTR + KP*VSTR + QT*SSTR + KP + QT + 2*KP) * 4)   // 91520

__global__ __launch_bounds__(256, 2) void attn_mma(const float* __restrict__ qkv,
                                                   const int* __restrict__ am,
                                                   __half* __restrict__ o)
{
    extern __shared__ float sf[];
    float* sQ  = sf;
    float* sKV = sQ + QT * QSTR;
    float* sS  = sKV + KP * VSTR;
    float* sAm = sS + QT * SSTR;
    float* sDen = sAm + KP;
    int* sLo = (int*)(sDen + QT);
    int* sHi = sLo + KP;

    uint32_t sQb  = smem_u32(sQ);
    uint32_t sKVb = smem_u32(sKV);
    uint32_t sSb  = smem_u32(sS);

    int tid = threadIdx.x;
    int lane = tid & 31, wid = tid >> 5;
    int q0 = blockIdx.x * QT;
    int h = blockIdx.y & 15;
    int b = blockIdx.y >> 4;

    int koff = max(0, q0 - WINDOW - NGLOB);
    int NK = min(KP - 16, q0 + QT);          // min(176, q0+32)

    const float* qbase = qkv + ((long)b * SS) * (3 * DD) + h * DH;

#pragma unroll
    for (int t = 0; t < 2; t++) {
        int f = tid + t * 256;
        int row = f >> 4, ch = f & 15;
        float4 v = *(const float4*)(qbase + (long)(q0 + row) * (3 * DD) + ch * 4);
        v.x = tf32rf(v.x); v.y = tf32rf(v.y); v.z = tf32rf(v.z); v.w = tf32rf(v.w);
        *(float4*)(sQ + row * QSTR + ch * 4) = v;
    }
#pragma unroll
    for (int t = 0; t < 12; t++) {
        int f = tid + t * 256;
        int idx = f >> 4, ch = f & 15;
        float4 v = make_float4(0.f, 0.f, 0.f, 0.f);
        if (idx < NK) {
            int key = idx + (idx < NGLOB ? 0 : koff);
            v = *(const float4*)(qbase + (long)key * (3 * DD) + DD + ch * 4);
            v.x = tf32rf(v.x); v.y = tf32rf(v.y); v.z = tf32rf(v.z); v.w = tf32rf(v.w);
        }
        *(float4*)(sKV + idx * KSTR + ch * 4) = v;
    }
    if (tid < KP) {
        int idx = tid;
        float a = NEGV;
        int lo = 0x7fffffff, hi = 0x7fffffff;
        if (idx < NK) {
            int key = idx + (idx < NGLOB ? 0 : koff);
            a = (am[b * SS + key] == 0) ? NEGV : 0.f;
            lo = key;
            hi = (idx < NGLOB) ? 0x7fffffff : key + WINDOW;
        }
        sAm[idx] = a;
        sLo[idx] = lo;
        sHi[idx] = hi;
    }
    __syncthreads();

    int g = lane >> 3;
    int rl = lane & 7;
    // ---- phase 1: S = Q @ K^T ----
    int wm = (wid & 1) * 16;
    int wn = (wid >> 1) * 48;
    {
        float acc[6][4];
#pragma unroll
        for (int j = 0; j < 6; j++)
#pragma unroll
            for (int c = 0; c < 4; c++) acc[j][c] = 0.f;

        uint32_t aQ = sQb + (wm + (g & 1) * 8 + rl) * (QSTR * 4) + (g >> 1) * 16;
        uint32_t bK = sKVb + (wn + (g >> 1) * 8 + rl) * (KSTR * 4) + (g & 1) * 16;
#pragma unroll
        for (int ks = 0; ks < 8; ks++) {
            uint32_t af[4], bf[6][2];
            LDSM_X4(af[0], af[1], af[2], af[3], aQ + ks * 32);
#pragma unroll
            for (int p = 0; p < 3; p++)
                LDSM_X4(bf[2*p][0], bf[2*p][1], bf[2*p+1][0], bf[2*p+1][1],
                        bK + p * (16 * KSTR * 4) + ks * 32);
#pragma unroll
            for (int nt = 0; nt < 6; nt++)
                MMA_TF32(acc[nt], af, bf[nt]);
        }

        int r0 = wm + (lane >> 2);
        int r1 = r0 + 8;
        int qa0 = q0 + r0, qa1 = q0 + r1;
#pragma unroll
        for (int nt = 0; nt < 6; nt++) {
            int col = wn + nt * 8 + 2 * (lane & 3);
#pragma unroll
            for (int cc = 0; cc < 2; cc++) {
                int cidx = col + cc;
                int lo = sLo[cidx], hi = sHi[cidx];
                float amv = sAm[cidx];
                bool ok0 = (qa0 >= lo) && (qa0 <= hi);
                bool ok1 = (qa1 >= lo) && (qa1 <= hi);
                sS[r0 * SSTR + cidx] = ok0 ? acc[nt][cc] * 0.125f + amv : NEGV;
                sS[r1 * SSTR + cidx] = ok1 ? acc[nt][2 + cc] * 0.125f + amv : NEGV;
            }
        }
    }
    __syncthreads();

#pragma unroll
    for (int t = 0; t < 12; t++) {
        int f = tid + t * 256;
        int idx = f >> 4, ch = f & 15;
        float4 v = make_float4(0.f, 0.f, 0.f, 0.f);
        if (idx < NK) {
            int key = idx + (idx < NGLOB ? 0 : koff);
            v = *(const float4*)(qbase + (long)key * (3 * DD) + 2 * DD + ch * 4);
            v.x = tf32rf(v.x); v.y = tf32rf(v.y); v.z = tf32rf(v.z); v.w = tf32rf(v.w);
        }
        *(float4*)(sKV + idx * VSTR + ch * 4) = v;
    }

#pragma unroll
    for (int i = 0; i < 4; i++) {
        int r = wid * 4 + i;
        float v[6];
#pragma unroll
        for (int j = 0; j < 6; j++) v[j] = sS[r * SSTR + lane + j * 32];
        float mx = v[0];
#pragma unroll
        for (int j = 1; j < 6; j++) mx = fmaxf(mx, v[j]);
#pragma unroll
        for (int off = 16; off > 0; off >>= 1) mx = fmaxf(mx, __shfl_xor_sync(0xffffffffu, mx, off));
        float sum = 0.f;
#pragma unroll
        for (int j = 0; j < 6; j++) {
            float e = __expf(v[j] - mx);
            e = tf32rf(e);
            sum += e;
            sS[r * SSTR + lane + j * 32] = e;
        }
#pragma unroll
        for (int off = 16; off > 0; off >>= 1) sum += __shfl_xor_sync(0xffffffffu, sum, off);
        if (lane == 0) sDen[r] = sum;
    }
    __syncthreads();

    {
        int wm2 = (wid & 1) * 16;
        int wn2 = (wid >> 1) * 16;
        float acc2[2][4];
#pragma unroll
        for (int j = 0; j < 2; j++)
#pragma unroll
            for (int c = 0; c < 4; c++) acc2[j][c] = 0.f;

        uint32_t aS = sSb + (wm2 + (g & 1) * 8 + rl) * (SSTR * 4) + (g >> 1) * 16;
#pragma unroll
        for (int ks = 0; ks < 24; ks++) {
            uint32_t af[4];
            LDSM_X4(af[0], af[1], af[2], af[3], aS + ks * 32);
            int k0 = ks * 8 + (lane & 3);
            int nb = wn2 + (lane >> 2);
            uint32_t bf[2][2];
#pragma unroll
            for (int nt = 0; nt < 2; nt++) {
                bf[nt][0] = __float_as_uint(sKV[k0 * VSTR + nb + nt * 8]);
                bf[nt][1] = __float_as_uint(sKV[(k0 + 4) * VSTR + nb + nt * 8]);
            }
#pragma unroll
            for (int nt = 0; nt < 2; nt++)
                MMA_TF32(acc2[nt], af, bf[nt]);
        }

        int r0o = wm2 + (lane >> 2);
        int r1o = r0o + 8;
        float inv0 = 1.f / sDen[r0o];
        float inv1 = 1.f / sDen[r1o];
        __half* ob0 = o + ((long)(b * SS + q0 + r0o)) * DD + h * DH;
        __half* ob1 = o + ((long)(b * SS + q0 + r1o)) * DD + h * DH;
#pragma unroll
        for (int nt = 0; nt < 2; nt++) {
            int col = wn2 + nt * 8 + 2 * (lane & 3);
            *(__half2*)(ob0 + col) = __floats2half2_rn(acc2[nt][0] * inv0, acc2[nt][1] * inv0);
            *(__half2*)(ob1 + col) = __floats2half2_rn(acc2[nt][2] * inv1, acc2[nt][3] * inv1);
        }
    }
}

// ---------------- launch ----------------
extern "C" void kernel_launch(void* const* d_in, const int* in_sizes, int n_in,
                              void* d_out, int out_size)
{
    const float* x     = (const float*)d_in[0];
    const int*   am    = (const int*)  d_in[1];
    const float* w_in  = (const float*)d_in[2];
    const float* b_in  = (const float*)d_in[3];
    const float* w_out = (const float*)d_in[4];
    const float* b_out = (const float*)d_in[5];
    const float* g1    = (const float*)d_in[6];
    const float* bl1   = (const float*)d_in[7];
    const float* g2    = (const float*)d_in[8];
    const float* bl2   = (const float*)d_in[9];
    const float* w1    = (const float*)d_in[10];
    const float* b1    = (const float*)d_in[11];
    const float* w2    = (const float*)d_in[12];
    const float* b2    = (const float*)d_in[13];
    float* out = (float*)d_out;

    void *p_hln, *p_qkv, *p_o, *p_x1, *p_h2, *p_wh;
    cudaGetSymbolAddress(&p_hln, g_hln);
    cudaGetSymbolAddress(&p_qkv, g_qkv);
    cudaGetSymbolAddress(&p_o,   g_o);
    cudaGetSymbolAddress(&p_x1,  g_x1);
    cudaGetSymbolAddress(&p_h2,  g_h2);
    cudaGetSymbolAddress(&p_wh,  g_wh);
    __half* hln = (__half*)p_hln;
    float*  qkv = (float*)p_qkv;
    __half* o   = (__half*)p_o;
    float*  x1  = (float*)p_x1;
    __half* h2  = (__half*)p_h2;
    __half* wh  = (__half*)p_wh;

    cudaFuncSetAttribute(gemm_h<false, false, false>, cudaFuncAttributeMaxDynamicSharedMemorySize, GEMM_SMEM);
    cudaFuncSetAttribute(gemm_h<false, true,  false>, cudaFuncAttributeMaxDynamicSharedMemorySize, GEMM_SMEM);
    cudaFuncSetAttribute(gemm_h<true,  false, true >, cudaFuncAttributeMaxDynamicSharedMemorySize, GEMM_SMEM);
    cudaFuncSetAttribute(attn_mma, cudaFuncAttributeMaxDynamicSharedMemorySize, ATTN_SMEM);

    // 0. all weights -> fp16
    wprep_kernel<<<WTOTAL / (256 * 4), 256>>>(w_in, w_out, w1, w2);
    // 1. LN1 -> fp16
    ln_kernel<<<ROWS, 256>>>(x, g1, bl1, hln);
    // 2. qkv = hln @ w_in^T + b_in   (fp16 mma, fp32 out)
    gemm_h<false, false, false><<<dim3(3 * DD / 128, ROWS / 128), 256, GEMM_SMEM>>>(hln, wh + OFF_WIN, b_in, nullptr, qkv, ROWS, 3 * DD, DD);
    // 3. attention -> o (fp16)
    attn_mma<<<dim3(SS / QT, BB * HH), 256, ATTN_SMEM>>>(qkv, am, o);
    // 4. x1 = x + o @ w_out^T + b_out   (fp16 mma, fp32 out)
    gemm_h<false, true, false><<<dim3(DD / 128, ROWS / 128), 256, GEMM_SMEM>>>(o, wh + OFF_WOUT, b_out, x, x1, ROWS, DD, DD);
    // 5. LN2 -> fp16
    ln_kernel<<<ROWS, 256>>>(x1, g2, bl2, hln);
    // 6. h2 = gelu(hln @ w1^T + b1)   (fp16 mma, fp16 out)
    gemm_h<true, false, true><<<dim3(FF / 128, ROWS / 128), 256, GEMM_SMEM>>>(hln, wh + OFF_W1, b1, nullptr, h2, ROWS, FF, DD);
    // 7. out = x1 + h2 @ w2^T + b2   (fp16 mma, fp32 out)
    gemm_h<false, true, false><<<dim3(DD / 128, ROWS / 128), 256, GEMM_SMEM>>>(h2, wh + OFF_W2, b2, x1, out, ROWS, DD, FF);
}

// round 14
// speedup vs baseline: 1.8369x; 1.0573x over previous
#include <cuda_runtime.h>
#include <cuda_fp16.h>
#include <math.h>
#include <cstdint>

// Problem constants
#define BB 2
#define SS 2048
#define DD 1024
#define HH 16
#define DH 64
#define FF 4096
#define ROWS (BB*SS)          // 4096
#define WINDOW 128
#define NGLOB 16
#define NEGV -1e9f

// input-ordered offsets inside g_wh (all weights fp16)
#define OFF_WIN  0
#define OFF_WOUT (3*DD*DD)
#define OFF_W1   (OFF_WOUT + DD*DD)
#define OFF_W2   (OFF_W1 + FF*DD)
#define WTOTAL   (OFF_W2 + DD*FF)

// ---------------- scratch ----------------
__device__ __half g_hln[ROWS * DD];         // LN outputs (fp16)
__device__ __half g_qkvh[ROWS * 3 * DD];    // qkv projection (fp16)
__device__ __half g_o  [ROWS * DD];         // attention output (fp16)
__device__ float  g_x1 [ROWS * DD];         // x + attn residual (fp32)
__device__ __half g_h2 [ROWS * FF];         // gelu hidden (fp16)
__device__ __half g_wh [WTOTAL];            // fp16 weights

// ---------------- helpers ----------------
__device__ __forceinline__ float tf32rf(float f) {
    uint32_t u;
    asm("cvt.rna.tf32.f32 %0, %1;" : "=r"(u) : "f"(f));
    return __uint_as_float(u);
}
__device__ __forceinline__ uint32_t smem_u32(const void* p) {
    uint32_t a;
    asm("{ .reg .u64 t; cvta.to.shared.u64 t, %1; cvt.u32.u64 %0, t; }" : "=r"(a) : "l"(p));
    return a;
}
#define CP_ASYNC16(sdst, gsrc) \
    asm volatile("cp.async.cg.shared.global [%0], [%1], 16;" :: "r"(sdst), "l"(gsrc))
#define CP_COMMIT() asm volatile("cp.async.commit_group;" ::: "memory")
#define CP_WAIT1()  asm volatile("cp.async.wait_group 1;" ::: "memory")

#define LDSM_X4(r0, r1, r2, r3, addr) \
    asm volatile("ldmatrix.sync.aligned.m8n8.x4.shared.b16 {%0,%1,%2,%3}, [%4];" \
        : "=r"(r0), "=r"(r1), "=r"(r2), "=r"(r3) : "r"(addr))

#define MMA_TF32(c, a, b) \
    asm volatile("mma.sync.aligned.m16n8k8.row.col.f32.tf32.tf32.f32 " \
        "{%0,%1,%2,%3}, {%4,%5,%6,%7}, {%8,%9}, {%0,%1,%2,%3};" \
        : "+f"((c)[0]), "+f"((c)[1]), "+f"((c)[2]), "+f"((c)[3]) \
        : "r"((a)[0]), "r"((a)[1]), "r"((a)[2]), "r"((a)[3]), \
          "r"((b)[0]), "r"((b)[1]))

#define MMA_F16(c, a, b) \
    asm volatile("mma.sync.aligned.m16n8k16.row.col.f32.f16.f16.f32 " \
        "{%0,%1,%2,%3}, {%4,%5,%6,%7}, {%8,%9}, {%0,%1,%2,%3};" \
        : "+f"((c)[0]), "+f"((c)[1]), "+f"((c)[2]), "+f"((c)[3]) \
        : "r"((a)[0]), "r"((a)[1]), "r"((a)[2]), "r"((a)[3]), \
          "r"((b)[0]), "r"((b)[1]))

// ---------------- weight prep: all four -> fp16 ----------------
__global__ __launch_bounds__(256) void wprep_kernel(const float* __restrict__ w_in,
                                                    const float* __restrict__ w_out,
                                                    const float* __restrict__ w1,
                                                    const float* __restrict__ w2)
{
    long i = ((long)blockIdx.x * 256 + threadIdx.x) * 4;
    float4 v;
    if (i < OFF_WOUT)      v = *(const float4*)(w_in + i);
    else if (i < OFF_W1)   v = *(const float4*)(w_out + (i - OFF_WOUT));
    else if (i < OFF_W2)   v = *(const float4*)(w1 + (i - OFF_W1));
    else                   v = *(const float4*)(w2 + (i - OFF_W2));
    __half2 p0 = __floats2half2_rn(v.x, v.y);
    __half2 p1 = __floats2half2_rn(v.z, v.w);
    uint2 pk = make_uint2(*(uint32_t*)&p0, *(uint32_t*)&p1);
    *(uint2*)(g_wh + i) = pk;
}

#define RSTR 144                            // smem row stride bytes
#define STG  (128 * RSTR)                   // 18432 per matrix per stage
#define NSTAGES 3
#define GEMM_SMEM (2 * NSTAGES * STG)       // 110592

// ---------------- fp16 GEMM: CTA 128x128, BK=64 halves, 8 warps 2Mx4N ----------------
template <bool GELU, bool RES, bool OUTH>
__global__ __launch_bounds__(256, 2) void gemm_h(const __half* __restrict__ A,
                                                 const __half* __restrict__ W,
                                                 const float* __restrict__ bias,
                                                 const float* __restrict__ res,
                                                 void* __restrict__ Cv,
                                                 int M, int N, int K)
{
    extern __shared__ char smem[];
    uint32_t sA = smem_u32(smem);
    uint32_t sB = sA + NSTAGES * STG;

    int tid = threadIdx.x;
    int lane = tid & 31, wid = tid >> 5;
    int m0 = blockIdx.y * 128;
    int n0 = blockIdx.x * 128;
    int wm = (wid & 1) * 64;
    int wn = (wid >> 1) * 32;

    int r0 = tid >> 3;
    int c16 = tid & 7;
    const __half* Agp = A + (long)(m0 + r0) * K + c16 * 8;
    const __half* Bgp = W + (long)(n0 + r0) * K + c16 * 8;
    uint32_t sa = sA + r0 * RSTR + c16 * 16;
    uint32_t sb = sB + r0 * RSTR + c16 * 16;

#define ISSUE_STAGE(s) do { \
    long k0g = (long)(s) * 64; \
    uint32_t so = ((s) % NSTAGES) * STG; \
    _Pragma("unroll") \
    for (int i_ = 0; i_ < 4; i_++) { \
        CP_ASYNC16(sa + so + i_ * (32 * RSTR), Agp + (long)(32 * i_) * K + k0g); \
        CP_ASYNC16(sb + so + i_ * (32 * RSTR), Bgp + (long)(32 * i_) * K + k0g); \
    } \
    CP_COMMIT(); } while (0)

    int g = lane >> 3;
    int rl = lane & 7;
    uint32_t aoff = (uint32_t)(((g & 1) * 8 + rl + wm) * RSTR + (g >> 1) * 16);
    uint32_t boff = (uint32_t)(((g >> 1) * 8 + rl + wn) * RSTR + (g & 1) * 16);

    float acc[4][4][4];
#pragma unroll
    for (int i = 0; i < 4; i++)
#pragma unroll
        for (int j = 0; j < 4; j++)
#pragma unroll
            for (int c = 0; c < 4; c++) acc[i][j][c] = 0.f;

    int nIter = K >> 6;
    ISSUE_STAGE(0);
    ISSUE_STAGE(1);

    for (int it = 0; it < nIter; it++) {
        CP_WAIT1();
        __syncthreads();
        if (it + 2 < nIter) { ISSUE_STAGE(it + 2); } else { CP_COMMIT(); }

        uint32_t slot = (uint32_t)((it % NSTAGES) * STG);
        uint32_t abase = sA + slot + aoff;
        uint32_t bbase = sB + slot + boff;
#pragma unroll
        for (int ks = 0; ks < 4; ks++) {
            uint32_t af[4][4], bf[4][2];
#pragma unroll
            for (int mi = 0; mi < 4; mi++)
                LDSM_X4(af[mi][0], af[mi][1], af[mi][2], af[mi][3],
                        abase + mi * (16 * RSTR) + ks * 32);
#pragma unroll
            for (int p = 0; p < 2; p++)
                LDSM_X4(bf[2*p][0], bf[2*p][1], bf[2*p+1][0], bf[2*p+1][1],
                        bbase + p * (16 * RSTR) + ks * 32);
#pragma unroll
            for (int mi = 0; mi < 4; mi++)
#pragma unroll
                for (int ni = 0; ni < 4; ni++)
                    MMA_F16(acc[mi][ni], af[mi], bf[ni]);
        }
    }
#undef ISSUE_STAGE

#pragma unroll
    for (int mi = 0; mi < 4; mi++) {
        long r_lo = m0 + wm + mi * 16 + (lane >> 2);
        long r_hi = r_lo + 8;
#pragma unroll
        for (int ni = 0; ni < 4; ni++) {
            int col = n0 + wn + ni * 8 + (lane & 3) * 2;
            float2 bv = *(const float2*)(bias + col);
            float v0 = acc[mi][ni][0] + bv.x;
            float v1 = acc[mi][ni][1] + bv.y;
            float v2 = acc[mi][ni][2] + bv.x;
            float v3 = acc[mi][ni][3] + bv.y;
            if (RES) {
                float2 rr0 = *(const float2*)(res + r_lo * N + col);
                float2 rr1 = *(const float2*)(res + r_hi * N + col);
                v0 += rr0.x; v1 += rr0.y; v2 += rr1.x; v3 += rr1.y;
            }
            if (GELU) {
                v0 = 0.5f * v0 * (1.0f + erff(v0 * 0.70710678118654752f));
                v1 = 0.5f * v1 * (1.0f + erff(v1 * 0.70710678118654752f));
                v2 = 0.5f * v2 * (1.0f + erff(v2 * 0.70710678118654752f));
                v3 = 0.5f * v3 * (1.0f + erff(v3 * 0.70710678118654752f));
            }
            if (OUTH) {
                __half* C = (__half*)Cv;
                *(__half2*)(C + r_lo * N + col) = __floats2half2_rn(v0, v1);
                *(__half2*)(C + r_hi * N + col) = __floats2half2_rn(v2, v3);
            } else {
                float* C = (float*)Cv;
                *(float2*)(C + r_lo * N + col) = make_float2(v0, v1);
                *(float2*)(C + r_hi * N + col) = make_float2(v2, v3);
            }
        }
    }
}

// ---------------- LayerNorm (fp32 in, fp16 out) ----------------
__global__ __launch_bounds__(256) void ln_kernel(const float* __restrict__ x,
                                                 const float* __restrict__ g,
                                                 const float* __restrict__ bt,
                                                 __half* __restrict__ out)
{
    int row = blockIdx.x;
    const float* xr = x + (long)row * DD;
    float v[4];
    float s = 0.f, s2 = 0.f;
#pragma unroll
    for (int i = 0; i < 4; i++) {
        v[i] = xr[threadIdx.x + i * 256];
        s += v[i];
        s2 += v[i] * v[i];
    }
    int lane = threadIdx.x & 31, warp = threadIdx.x >> 5;
#pragma unroll
    for (int off = 16; off > 0; off >>= 1) {
        s  += __shfl_xor_sync(0xffffffffu, s,  off);
        s2 += __shfl_xor_sync(0xffffffffu, s2, off);
    }
    __shared__ float sm[8], sm2[8];
    if (lane == 0) { sm[warp] = s; sm2[warp] = s2; }
    __syncthreads();
    if (threadIdx.x == 0) {
        float a = 0.f, b = 0.f;
#pragma unroll
        for (int i = 0; i < 8; i++) { a += sm[i]; b += sm2[i]; }
        float mean = a * (1.0f / DD);
        float var  = b * (1.0f / DD) - mean * mean;
        sm[0] = mean;
        sm2[0] = rsqrtf(var + 1e-5f);
    }
    __syncthreads();
    float mean = sm[0], inv = sm2[0];
    __half* orow = out + (long)row * DD;
#pragma unroll
    for (int i = 0; i < 4; i++) {
        int c = threadIdx.x + i * 256;
        orow[c] = __float2half((v[i] - mean) * inv * g[c] + bt[c]);
    }
}

// ---------------- mma-tiled sparse attention (fp16 QK front-end) ----------------
// QT=32, KP=192. Q/K in fp16 smem (stride 72 halves = 144B, gemm_h fragment scheme).
// Phase1: S = Q@K^T via MMA_F16, 4 k16-steps. V converted fp16->fp32; PV stays tf32.
#define QT 32
#define KP 192
#define HSTR 72                  // halves per row (144B)
#define VSTR 72                  // floats per row (V tile)
#define SSTR 196
// smem bytes: Qh 4608 | Vf 55296 (K fp16 aliases its start) | S 25088 | am 768 | den 128 | lo/hi 1536
#define ATTN_SMEM (4608 + 55296 + 25088 + 768 + 128 + 1536)   // 87424

__global__ __launch_bounds__(256, 2) void attn_mma(const __half* __restrict__ qkv,
                                                   const int* __restrict__ am,
                                                   __half* __restrict__ o)
{
    extern __shared__ char sm8[];
    __half* sQh = (__half*)sm8;                    // 32 x 72 halves
    float*  sV  = (float*)(sm8 + 4608);            // 192 x 72 floats
    __half* sKh = (__half*)sV;                     // K fp16 aliases V region
    float*  sS  = (float*)(sm8 + 4608 + 55296);    // 32 x 196
    float*  sAm = sS + QT * SSTR;
    float*  sDen = sAm + KP;
    int* sLo = (int*)(sDen + QT);
    int* sHi = sLo + KP;

    uint32_t sQb = smem_u32(sQh);
    uint32_t sKb = smem_u32(sKh);
    uint32_t sSb = smem_u32(sS);

    int tid = threadIdx.x;
    int lane = tid & 31, wid = tid >> 5;
    int q0 = blockIdx.x * QT;
    int h = blockIdx.y & 15;
    int b = blockIdx.y >> 4;

    int koff = max(0, q0 - WINDOW - NGLOB);
    int NK = min(KP - 16, q0 + QT);          // min(176, q0+32)

    const __half* qb = qkv + ((long)b * SS) * (3 * DD) + h * DH;

    // ---- load Q fp16: 32 rows x 8 chunks of 16B = 256 chunks ----
    {
        int row = tid >> 3, ch = tid & 7;
        uint4 v = *(const uint4*)(qb + (long)(q0 + row) * (3 * DD) + ch * 8);
        *(uint4*)(sQh + row * HSTR + ch * 8) = v;
    }
    // ---- load K fp16: 192 rows x 8 chunks = 1536 chunks (6/thread) ----
#pragma unroll
    for (int t = 0; t < 6; t++) {
        int f = tid + t * 256;
        int idx = f >> 3, ch = f & 7;
        uint4 v = make_uint4(0, 0, 0, 0);
        if (idx < NK) {
            int key = idx + (idx < NGLOB ? 0 : koff);
            v = *(const uint4*)(qb + (long)key * (3 * DD) + DD + ch * 8);
        }
        *(uint4*)(sKh + idx * HSTR + ch * 8) = v;
    }
    if (tid < KP) {
        int idx = tid;
        float a = NEGV;
        int lo = 0x7fffffff, hi = 0x7fffffff;
        if (idx < NK) {
            int key = idx + (idx < NGLOB ? 0 : koff);
            a = (am[b * SS + key] == 0) ? NEGV : 0.f;
            lo = key;
            hi = (idx < NGLOB) ? 0x7fffffff : key + WINDOW;
        }
        sAm[idx] = a;
        sLo[idx] = lo;
        sHi[idx] = hi;
    }
    __syncthreads();

    int g = lane >> 3;
    int rl = lane & 7;
    // ---- phase 1: S = Q @ K^T (fp16 mma, 4 k16 steps; warps 2M x 4N, 16q x 48k) ----
    int wm = (wid & 1) * 16;
    int wn = (wid >> 1) * 48;
    {
        float acc[6][4];
#pragma unroll
        for (int j = 0; j < 6; j++)
#pragma unroll
            for (int c = 0; c < 4; c++) acc[j][c] = 0.f;

        uint32_t aQ = sQb + (wm + (g & 1) * 8 + rl) * 144 + (g >> 1) * 16;
        uint32_t bK = sKb + (wn + (g >> 1) * 8 + rl) * 144 + (g & 1) * 16;
#pragma unroll
        for (int ks = 0; ks < 4; ks++) {
            uint32_t af[4], bf[6][2];
            LDSM_X4(af[0], af[1], af[2], af[3], aQ + ks * 32);
#pragma unroll
            for (int p = 0; p < 3; p++)
                LDSM_X4(bf[2*p][0], bf[2*p][1], bf[2*p+1][0], bf[2*p+1][1],
                        bK + p * (16 * 144) + ks * 32);
#pragma unroll
            for (int nt = 0; nt < 6; nt++)
                MMA_F16(acc[nt], af, bf[nt]);
        }

        int r0 = wm + (lane >> 2);
        int r1 = r0 + 8;
        int qa0 = q0 + r0, qa1 = q0 + r1;
#pragma unroll
        for (int nt = 0; nt < 6; nt++) {
            int col = wn + nt * 8 + 2 * (lane & 3);
#pragma unroll
            for (int cc = 0; cc < 2; cc++) {
                int cidx = col + cc;
                int lo = sLo[cidx], hi = sHi[cidx];
                float amv = sAm[cidx];
                bool ok0 = (qa0 >= lo) && (qa0 <= hi);
                bool ok1 = (qa1 >= lo) && (qa1 <= hi);
                sS[r0 * SSTR + cidx] = ok0 ? acc[nt][cc] * 0.125f + amv : NEGV;
                sS[r1 * SSTR + cidx] = ok1 ? acc[nt][2 + cc] * 0.125f + amv : NEGV;
            }
        }
    }
    __syncthreads();

    // ---- load V fp16 -> fp32 smem (overwrites K region) ----
#pragma unroll
    for (int t = 0; t < 6; t++) {
        int f = tid + t * 256;
        int idx = f >> 3, ch = f & 7;
        float4 f0 = make_float4(0.f, 0.f, 0.f, 0.f);
        float4 f1 = make_float4(0.f, 0.f, 0.f, 0.f);
        if (idx < NK) {
            int key = idx + (idx < NGLOB ? 0 : koff);
            uint4 raw = *(const uint4*)(qb + (long)key * (3 * DD) + 2 * DD + ch * 8);
            float2 a0 = __half22float2(*(__half2*)&raw.x);
            float2 a1 = __half22float2(*(__half2*)&raw.y);
            float2 a2 = __half22float2(*(__half2*)&raw.z);
            float2 a3 = __half22float2(*(__half2*)&raw.w);
            f0 = make_float4(a0.x, a0.y, a1.x, a1.y);
            f1 = make_float4(a2.x, a2.y, a3.x, a3.y);
        }
        *(float4*)(sV + idx * VSTR + ch * 8) = f0;
        *(float4*)(sV + idx * VSTR + ch * 8 + 4) = f1;
    }

    // ---- phase 2: softmax rows (warp w: rows w*4 .. w*4+3) ----
#pragma unroll
    for (int i = 0; i < 4; i++) {
        int r = wid * 4 + i;
        float v[6];
#pragma unroll
        for (int j = 0; j < 6; j++) v[j] = sS[r * SSTR + lane + j * 32];
        float mx = v[0];
#pragma unroll
        for (int j = 1; j < 6; j++) mx = fmaxf(mx, v[j]);
#pragma unroll
        for (int off = 16; off > 0; off >>= 1) mx = fmaxf(mx, __shfl_xor_sync(0xffffffffu, mx, off));
        float sum = 0.f;
#pragma unroll
        for (int j = 0; j < 6; j++) {
            float e = __expf(v[j] - mx);
            e = tf32rf(e);
            sum += e;
            sS[r * SSTR + lane + j * 32] = e;
        }
#pragma unroll
        for (int off = 16; off > 0; off >>= 1) sum += __shfl_xor_sync(0xffffffffu, sum, off);
        if (lane == 0) sDen[r] = sum;
    }
    __syncthreads();

    // ---- phase 3: O = P @ V (tf32, unchanged) ----
    {
        int wm2 = (wid & 1) * 16;
        int wn2 = (wid >> 1) * 16;
        float acc2[2][4];
#pragma unroll
        for (int j = 0; j < 2; j++)
#pragma unroll
            for (int c = 0; c < 4; c++) acc2[j][c] = 0.f;

        uint32_t aS = sSb + (wm2 + (g & 1) * 8 + rl) * (SSTR * 4) + (g >> 1) * 16;
#pragma unroll
        for (int ks = 0; ks < 24; ks++) {
            uint32_t af[4];
            LDSM_X4(af[0], af[1], af[2], af[3], aS + ks * 32);
            int k0 = ks * 8 + (lane & 3);
            int nb = wn2 + (lane >> 2);
            uint32_t bf[2][2];
#pragma unroll
            for (int nt = 0; nt < 2; nt++) {
                bf[nt][0] = __float_as_uint(sV[k0 * VSTR + nb + nt * 8]);
                bf[nt][1] = __float_as_uint(sV[(k0 + 4) * VSTR + nb + nt * 8]);
            }
#pragma unroll
            for (int nt = 0; nt < 2; nt++)
                MMA_TF32(acc2[nt], af, bf[nt]);
        }

        int r0o = wm2 + (lane >> 2);
        int r1o = r0o + 8;
        float inv0 = 1.f / sDen[r0o];
        float inv1 = 1.f / sDen[r1o];
        __half* ob0 = o + ((long)(b * SS + q0 + r0o)) * DD + h * DH;
        __half* ob1 = o + ((long)(b * SS + q0 + r1o)) * DD + h * DH;
#pragma unroll
        for (int nt = 0; nt < 2; nt++) {
            int col = wn2 + nt * 8 + 2 * (lane & 3);
            *(__half2*)(ob0 + col) = __floats2half2_rn(acc2[nt][0] * inv0, acc2[nt][1] * inv0);
            *(__half2*)(ob1 + col) = __floats2half2_rn(acc2[nt][2] * inv1, acc2[nt][3] * inv1);
        }
    }
}

// ---------------- launch ----------------
extern "C" void kernel_launch(void* const* d_in, const int* in_sizes, int n_in,
                              void* d_out, int out_size)
{
    const float* x     = (const float*)d_in[0];
    const int*   am    = (const int*)  d_in[1];
    const float* w_in  = (const float*)d_in[2];
    const float* b_in  = (const float*)d_in[3];
    const float* w_out = (const float*)d_in[4];
    const float* b_out = (const float*)d_in[5];
    const float* g1    = (const float*)d_in[6];
    const float* bl1   = (const float*)d_in[7];
    const float* g2    = (const float*)d_in[8];
    const float* bl2   = (const float*)d_in[9];
    const float* w1    = (const float*)d_in[10];
    const float* b1    = (const float*)d_in[11];
    const float* w2    = (const float*)d_in[12];
    const float* b2    = (const float*)d_in[13];
    float* out = (float*)d_out;

    void *p_hln, *p_qkv, *p_o, *p_x1, *p_h2, *p_wh;
    cudaGetSymbolAddress(&p_hln, g_hln);
    cudaGetSymbolAddress(&p_qkv, g_qkvh);
    cudaGetSymbolAddress(&p_o,   g_o);
    cudaGetSymbolAddress(&p_x1,  g_x1);
    cudaGetSymbolAddress(&p_h2,  g_h2);
    cudaGetSymbolAddress(&p_wh,  g_wh);
    __half* hln  = (__half*)p_hln;
    __half* qkvh = (__half*)p_qkv;
    __half* o    = (__half*)p_o;
    float*  x1   = (float*)p_x1;
    __half* h2   = (__half*)p_h2;
    __half* wh   = (__half*)p_wh;

    cudaFuncSetAttribute(gemm_h<false, false, true >, cudaFuncAttributeMaxDynamicSharedMemorySize, GEMM_SMEM);
    cudaFuncSetAttribute(gemm_h<false, true,  false>, cudaFuncAttributeMaxDynamicSharedMemorySize, GEMM_SMEM);
    cudaFuncSetAttribute(gemm_h<true,  false, true >, cudaFuncAttributeMaxDynamicSharedMemorySize, GEMM_SMEM);
    cudaFuncSetAttribute(attn_mma, cudaFuncAttributeMaxDynamicSharedMemorySize, ATTN_SMEM);

    // 0. all weights -> fp16
    wprep_kernel<<<WTOTAL / (256 * 4), 256>>>(w_in, w_out, w1, w2);
    // 1. LN1 -> fp16
    ln_kernel<<<ROWS, 256>>>(x, g1, bl1, hln);
    // 2. qkv = hln @ w_in^T + b_in   (fp16 mma, fp16 out)
    gemm_h<false, false, true><<<dim3(3 * DD / 128, ROWS / 128), 256, GEMM_SMEM>>>(hln, wh + OFF_WIN, b_in, nullptr, qkvh, ROWS, 3 * DD, DD);
    // 3. attention -> o (fp16)
    attn_mma<<<dim3(SS / QT, BB * HH), 256, ATTN_SMEM>>>(qkvh, am, o);
    // 4. x1 = x + o @ w_out^T + b_out   (fp16 mma, fp32 out)
    gemm_h<false, true, false><<<dim3(DD / 128, ROWS / 128), 256, GEMM_SMEM>>>(o, wh + OFF_WOUT, b_out, x, x1, ROWS, DD, DD);
    // 5. LN2 -> fp16
    ln_kernel<<<ROWS, 256>>>(x1, g2, bl2, hln);
    // 6. h2 = gelu(hln @ w1^T + b1)   (fp16 mma, fp16 out)
    gemm_h<true, false, true><<<dim3(FF / 128, ROWS / 128), 256, GEMM_SMEM>>>(hln, wh + OFF_W1, b1, nullptr, h2, ROWS, FF, DD);
    // 7. out = x1 + h2 @ w2^T + b2   (fp16 mma, fp32 out)
    gemm_h<false, true, false><<<dim3(DD / 128, ROWS / 128), 256, GEMM_SMEM>>>(h2, wh + OFF_W2, b2, x1, out, ROWS, DD, FF);
}

// round 15
// speedup vs baseline: 1.8637x; 1.0146x over previous
#include <cuda_runtime.h>
#include <cuda_fp16.h>
#include <math.h>
#include <cstdint>

// Problem constants
#define BB 2
#define SS 2048
#define DD 1024
#define HH 16
#define DH 64
#define FF 4096
#define ROWS (BB*SS)          // 4096
#define WINDOW 128
#define NGLOB 16
#define NEGV -1e9f

// input-ordered offsets inside g_wh (all weights fp16)
#define OFF_WIN  0
#define OFF_WOUT (3*DD*DD)
#define OFF_W1   (OFF_WOUT + DD*DD)
#define OFF_W2   (OFF_W1 + FF*DD)
#define WTOTAL   (OFF_W2 + DD*FF)

// ---------------- scratch ----------------
__device__ __half g_hln[ROWS * DD];         // LN outputs (fp16)
__device__ __half g_qkvh[ROWS * 3 * DD];    // qkv projection (fp16)
__device__ __half g_o  [ROWS * DD];         // attention output (fp16)
__device__ float  g_x1 [ROWS * DD];         // x + attn residual (fp32)
__device__ __half g_h2 [ROWS * FF];         // gelu hidden (fp16)
__device__ __half g_wh [WTOTAL];            // fp16 weights

// ---------------- helpers ----------------
__device__ __forceinline__ float tf32rf(float f) {
    uint32_t u;
    asm("cvt.rna.tf32.f32 %0, %1;" : "=r"(u) : "f"(f));
    return __uint_as_float(u);
}
__device__ __forceinline__ uint32_t smem_u32(const void* p) {
    uint32_t a;
    asm("{ .reg .u64 t; cvta.to.shared.u64 t, %1; cvt.u32.u64 %0, t; }" : "=r"(a) : "l"(p));
    return a;
}
#define CP_ASYNC16(sdst, gsrc) \
    asm volatile("cp.async.cg.shared.global [%0], [%1], 16;" :: "r"(sdst), "l"(gsrc))
#define CP_COMMIT() asm volatile("cp.async.commit_group;" ::: "memory")
#define CP_WAIT1()  asm volatile("cp.async.wait_group 1;" ::: "memory")

#define LDSM_X4(r0, r1, r2, r3, addr) \
    asm volatile("ldmatrix.sync.aligned.m8n8.x4.shared.b16 {%0,%1,%2,%3}, [%4];" \
        : "=r"(r0), "=r"(r1), "=r"(r2), "=r"(r3) : "r"(addr))

#define MMA_TF32(c, a, b) \
    asm volatile("mma.sync.aligned.m16n8k8.row.col.f32.tf32.tf32.f32 " \
        "{%0,%1,%2,%3}, {%4,%5,%6,%7}, {%8,%9}, {%0,%1,%2,%3};" \
        : "+f"((c)[0]), "+f"((c)[1]), "+f"((c)[2]), "+f"((c)[3]) \
        : "r"((a)[0]), "r"((a)[1]), "r"((a)[2]), "r"((a)[3]), \
          "r"((b)[0]), "r"((b)[1]))

#define MMA_F16(c, a, b) \
    asm volatile("mma.sync.aligned.m16n8k16.row.col.f32.f16.f16.f32 " \
        "{%0,%1,%2,%3}, {%4,%5,%6,%7}, {%8,%9}, {%0,%1,%2,%3};" \
        : "+f"((c)[0]), "+f"((c)[1]), "+f"((c)[2]), "+f"((c)[3]) \
        : "r"((a)[0]), "r"((a)[1]), "r"((a)[2]), "r"((a)[3]), \
          "r"((b)[0]), "r"((b)[1]))

// ---------------- weight prep: all four -> fp16 ----------------
__global__ __launch_bounds__(256) void wprep_kernel(const float* __restrict__ w_in,
                                                    const float* __restrict__ w_out,
                                                    const float* __restrict__ w1,
                                                    const float* __restrict__ w2)
{
    long i = ((long)blockIdx.x * 256 + threadIdx.x) * 4;
    float4 v;
    if (i < OFF_WOUT)      v = *(const float4*)(w_in + i);
    else if (i < OFF_W1)   v = *(const float4*)(w_out + (i - OFF_WOUT));
    else if (i < OFF_W2)   v = *(const float4*)(w1 + (i - OFF_W1));
    else                   v = *(const float4*)(w2 + (i - OFF_W2));
    __half2 p0 = __floats2half2_rn(v.x, v.y);
    __half2 p1 = __floats2half2_rn(v.z, v.w);
    uint2 pk = make_uint2(*(uint32_t*)&p0, *(uint32_t*)&p1);
    *(uint2*)(g_wh + i) = pk;
}

#define RSTR 144                            // smem row stride bytes
#define STG  (128 * RSTR)                   // 18432 per matrix per stage
#define NSTAGES 3
#define GEMM_SMEM (2 * NSTAGES * STG)       // 110592

// ---------------- fp16 GEMM: CTA 128x128, BK=64 halves, 8 warps 2Mx4N ----------------
template <bool GELU, bool RES, bool OUTH>
__global__ __launch_bounds__(256, 2) void gemm_h(const __half* __restrict__ A,
                                                 const __half* __restrict__ W,
                                                 const float* __restrict__ bias,
                                                 const float* __restrict__ res,
                                                 void* __restrict__ Cv,
                                                 int M, int N, int K)
{
    extern __shared__ char smem[];
    uint32_t sA = smem_u32(smem);
    uint32_t sB = sA + NSTAGES * STG;

    int tid = threadIdx.x;
    int lane = tid & 31, wid = tid >> 5;
    int m0 = blockIdx.y * 128;
    int n0 = blockIdx.x * 128;
    int wm = (wid & 1) * 64;
    int wn = (wid >> 1) * 32;

    int r0 = tid >> 3;
    int c16 = tid & 7;
    const __half* Agp = A + (long)(m0 + r0) * K + c16 * 8;
    const __half* Bgp = W + (long)(n0 + r0) * K + c16 * 8;
    uint32_t sa = sA + r0 * RSTR + c16 * 16;
    uint32_t sb = sB + r0 * RSTR + c16 * 16;

#define ISSUE_STAGE(s) do { \
    long k0g = (long)(s) * 64; \
    uint32_t so = ((s) % NSTAGES) * STG; \
    _Pragma("unroll") \
    for (int i_ = 0; i_ < 4; i_++) { \
        CP_ASYNC16(sa + so + i_ * (32 * RSTR), Agp + (long)(32 * i_) * K + k0g); \
        CP_ASYNC16(sb + so + i_ * (32 * RSTR), Bgp + (long)(32 * i_) * K + k0g); \
    } \
    CP_COMMIT(); } while (0)

    int g = lane >> 3;
    int rl = lane & 7;
    uint32_t aoff = (uint32_t)(((g & 1) * 8 + rl + wm) * RSTR + (g >> 1) * 16);
    uint32_t boff = (uint32_t)(((g >> 1) * 8 + rl + wn) * RSTR + (g & 1) * 16);

    float acc[4][4][4];
#pragma unroll
    for (int i = 0; i < 4; i++)
#pragma unroll
        for (int j = 0; j < 4; j++)
#pragma unroll
            for (int c = 0; c < 4; c++) acc[i][j][c] = 0.f;

    int nIter = K >> 6;
    ISSUE_STAGE(0);
    ISSUE_STAGE(1);

    for (int it = 0; it < nIter; it++) {
        CP_WAIT1();
        __syncthreads();
        if (it + 2 < nIter) { ISSUE_STAGE(it + 2); } else { CP_COMMIT(); }

        uint32_t slot = (uint32_t)((it % NSTAGES) * STG);
        uint32_t abase = sA + slot + aoff;
        uint32_t bbase = sB + slot + boff;
#pragma unroll
        for (int ks = 0; ks < 4; ks++) {
            uint32_t af[4][4], bf[4][2];
#pragma unroll
            for (int mi = 0; mi < 4; mi++)
                LDSM_X4(af[mi][0], af[mi][1], af[mi][2], af[mi][3],
                        abase + mi * (16 * RSTR) + ks * 32);
#pragma unroll
            for (int p = 0; p < 2; p++)
                LDSM_X4(bf[2*p][0], bf[2*p][1], bf[2*p+1][0], bf[2*p+1][1],
                        bbase + p * (16 * RSTR) + ks * 32);
#pragma unroll
            for (int mi = 0; mi < 4; mi++)
#pragma unroll
                for (int ni = 0; ni < 4; ni++)
                    MMA_F16(acc[mi][ni], af[mi], bf[ni]);
        }
    }
#undef ISSUE_STAGE

#pragma unroll
    for (int mi = 0; mi < 4; mi++) {
        long r_lo = m0 + wm + mi * 16 + (lane >> 2);
        long r_hi = r_lo + 8;
#pragma unroll
        for (int ni = 0; ni < 4; ni++) {
            int col = n0 + wn + ni * 8 + (lane & 3) * 2;
            float2 bv = *(const float2*)(bias + col);
            float v0 = acc[mi][ni][0] + bv.x;
            float v1 = acc[mi][ni][1] + bv.y;
            float v2 = acc[mi][ni][2] + bv.x;
            float v3 = acc[mi][ni][3] + bv.y;
            if (RES) {
                float2 rr0 = *(const float2*)(res + r_lo * N + col);
                float2 rr1 = *(const float2*)(res + r_hi * N + col);
                v0 += rr0.x; v1 += rr0.y; v2 += rr1.x; v3 += rr1.y;
            }
            if (GELU) {
                v0 = 0.5f * v0 * (1.0f + erff(v0 * 0.70710678118654752f));
                v1 = 0.5f * v1 * (1.0f + erff(v1 * 0.70710678118654752f));
                v2 = 0.5f * v2 * (1.0f + erff(v2 * 0.70710678118654752f));
                v3 = 0.5f * v3 * (1.0f + erff(v3 * 0.70710678118654752f));
            }
            if (OUTH) {
                __half* C = (__half*)Cv;
                *(__half2*)(C + r_lo * N + col) = __floats2half2_rn(v0, v1);
                *(__half2*)(C + r_hi * N + col) = __floats2half2_rn(v2, v3);
            } else {
                float* C = (float*)Cv;
                *(float2*)(C + r_lo * N + col) = make_float2(v0, v1);
                *(float2*)(C + r_hi * N + col) = make_float2(v2, v3);
            }
        }
    }
}

// ---------------- LayerNorm (fp32 in, fp16 out) ----------------
__global__ __launch_bounds__(256) void ln_kernel(const float* __restrict__ x,
                                                 const float* __restrict__ g,
                                                 const float* __restrict__ bt,
                                                 __half* __restrict__ out)
{
    int row = blockIdx.x;
    const float* xr = x + (long)row * DD;
    float v[4];
    float s = 0.f, s2 = 0.f;
#pragma unroll
    for (int i = 0; i < 4; i++) {
        v[i] = xr[threadIdx.x + i * 256];
        s += v[i];
        s2 += v[i] * v[i];
    }
    int lane = threadIdx.x & 31, warp = threadIdx.x >> 5;
#pragma unroll
    for (int off = 16; off > 0; off >>= 1) {
        s  += __shfl_xor_sync(0xffffffffu, s,  off);
        s2 += __shfl_xor_sync(0xffffffffu, s2, off);
    }
    __shared__ float sm[8], sm2[8];
    if (lane == 0) { sm[warp] = s; sm2[warp] = s2; }
    __syncthreads();
    if (threadIdx.x == 0) {
        float a = 0.f, b = 0.f;
#pragma unroll
        for (int i = 0; i < 8; i++) { a += sm[i]; b += sm2[i]; }
        float mean = a * (1.0f / DD);
        float var  = b * (1.0f / DD) - mean * mean;
        sm[0] = mean;
        sm2[0] = rsqrtf(var + 1e-5f);
    }
    __syncthreads();
    float mean = sm[0], inv = sm2[0];
    __half* orow = out + (long)row * DD;
#pragma unroll
    for (int i = 0; i < 4; i++) {
        int c = threadIdx.x + i * 256;
        orow[c] = __float2half((v[i] - mean) * inv * g[c] + bt[c]);
    }
}

// ---------------- mma-tiled sparse attention ----------------
// QT=32, KP=192. Q/K/V fp16 smem (stride 72 halves); Phase1 fp16 mma; PV: fp16 B
// operands converted to fp32 in registers, tf32 mma. ~59.8 KB smem -> 3 CTAs/SM.
#define QT 32
#define KP 192
#define HSTR 72                  // halves per row (144B)
#define SSTR 196
// smem bytes: Qh 4608 | KVh 27648 | S 25088 | am 768 | den 128 | lo/hi 1536
#define ATTN_SMEM (4608 + 27648 + 25088 + 768 + 128 + 1536)   // 59776

__global__ __launch_bounds__(256, 3) void attn_mma(const __half* __restrict__ qkv,
                                                   const int* __restrict__ am,
                                                   __half* __restrict__ o)
{
    extern __shared__ char sm8[];
    __half* sQh = (__half*)sm8;                    // 32 x 72 halves
    __half* sKV = (__half*)(sm8 + 4608);           // 192 x 72 halves (K, then V)
    float*  sS  = (float*)(sm8 + 4608 + 27648);    // 32 x 196
    float*  sAm = sS + QT * SSTR;
    float*  sDen = sAm + KP;
    int* sLo = (int*)(sDen + QT);
    int* sHi = sLo + KP;

    uint32_t sQb = smem_u32(sQh);
    uint32_t sKb = smem_u32(sKV);
    uint32_t sSb = smem_u32(sS);

    int tid = threadIdx.x;
    int lane = tid & 31, wid = tid >> 5;
    int q0 = blockIdx.x * QT;
    int h = blockIdx.y & 15;
    int b = blockIdx.y >> 4;

    int koff = max(0, q0 - WINDOW - NGLOB);
    int NK = min(KP - 16, q0 + QT);          // min(176, q0+32)

    const __half* qb = qkv + ((long)b * SS) * (3 * DD) + h * DH;

    // ---- load Q fp16: 32 rows x 8 chunks of 16B ----
    {
        int row = tid >> 3, ch = tid & 7;
        uint4 v = *(const uint4*)(qb + (long)(q0 + row) * (3 * DD) + ch * 8);
        *(uint4*)(sQh + row * HSTR + ch * 8) = v;
    }
    // ---- load K fp16: 192 rows x 8 chunks (6/thread) ----
#pragma unroll
    for (int t = 0; t < 6; t++) {
        int f = tid + t * 256;
        int idx = f >> 3, ch = f & 7;
        uint4 v = make_uint4(0, 0, 0, 0);
        if (idx < NK) {
            int key = idx + (idx < NGLOB ? 0 : koff);
            v = *(const uint4*)(qb + (long)key * (3 * DD) + DD + ch * 8);
        }
        *(uint4*)(sKV + idx * HSTR + ch * 8) = v;
    }
    if (tid < KP) {
        int idx = tid;
        float a = NEGV;
        int lo = 0x7fffffff, hi = 0x7fffffff;
        if (idx < NK) {
            int key = idx + (idx < NGLOB ? 0 : koff);
            a = (am[b * SS + key] == 0) ? NEGV : 0.f;
            lo = key;
            hi = (idx < NGLOB) ? 0x7fffffff : key + WINDOW;
        }
        sAm[idx] = a;
        sLo[idx] = lo;
        sHi[idx] = hi;
    }
    __syncthreads();

    int g = lane >> 3;
    int rl = lane & 7;
    // ---- phase 1: S = Q @ K^T (fp16 mma, 4 k16 steps; warps 2M x 4N, 16q x 48k) ----
    int wm = (wid & 1) * 16;
    int wn = (wid >> 1) * 48;
    {
        float acc[6][4];
#pragma unroll
        for (int j = 0; j < 6; j++)
#pragma unroll
            for (int c = 0; c < 4; c++) acc[j][c] = 0.f;

        uint32_t aQ = sQb + (wm + (g & 1) * 8 + rl) * 144 + (g >> 1) * 16;
        uint32_t bK = sKb + (wn + (g >> 1) * 8 + rl) * 144 + (g & 1) * 16;
#pragma unroll
        for (int ks = 0; ks < 4; ks++) {
            uint32_t af[4], bf[6][2];
            LDSM_X4(af[0], af[1], af[2], af[3], aQ + ks * 32);
#pragma unroll
            for (int p = 0; p < 3; p++)
                LDSM_X4(bf[2*p][0], bf[2*p][1], bf[2*p+1][0], bf[2*p+1][1],
                        bK + p * (16 * 144) + ks * 32);
#pragma unroll
            for (int nt = 0; nt < 6; nt++)
                MMA_F16(acc[nt], af, bf[nt]);
        }

        int r0 = wm + (lane >> 2);
        int r1 = r0 + 8;
        int qa0 = q0 + r0, qa1 = q0 + r1;
#pragma unroll
        for (int nt = 0; nt < 6; nt++) {
            int col = wn + nt * 8 + 2 * (lane & 3);
#pragma unroll
            for (int cc = 0; cc < 2; cc++) {
                int cidx = col + cc;
                int lo = sLo[cidx], hi = sHi[cidx];
                float amv = sAm[cidx];
                bool ok0 = (qa0 >= lo) && (qa0 <= hi);
                bool ok1 = (qa1 >= lo) && (qa1 <= hi);
                sS[r0 * SSTR + cidx] = ok0 ? acc[nt][cc] * 0.125f + amv : NEGV;
                sS[r1 * SSTR + cidx] = ok1 ? acc[nt][2 + cc] * 0.125f + amv : NEGV;
            }
        }
    }
    __syncthreads();

    // ---- load V fp16 (overwrites K region, same layout) ----
#pragma unroll
    for (int t = 0; t < 6; t++) {
        int f = tid + t * 256;
        int idx = f >> 3, ch = f & 7;
        uint4 v = make_uint4(0, 0, 0, 0);
        if (idx < NK) {
            int key = idx + (idx < NGLOB ? 0 : koff);
            v = *(const uint4*)(qb + (long)key * (3 * DD) + 2 * DD + ch * 8);
        }
        *(uint4*)(sKV + idx * HSTR + ch * 8) = v;
    }

    // ---- phase 2: softmax rows (warp w: rows w*4 .. w*4+3) ----
#pragma unroll
    for (int i = 0; i < 4; i++) {
        int r = wid * 4 + i;
        float v[6];
#pragma unroll
        for (int j = 0; j < 6; j++) v[j] = sS[r * SSTR + lane + j * 32];
        float mx = v[0];
#pragma unroll
        for (int j = 1; j < 6; j++) mx = fmaxf(mx, v[j]);
#pragma unroll
        for (int off = 16; off > 0; off >>= 1) mx = fmaxf(mx, __shfl_xor_sync(0xffffffffu, mx, off));
        float sum = 0.f;
#pragma unroll
        for (int j = 0; j < 6; j++) {
            float e = __expf(v[j] - mx);
            e = tf32rf(e);
            sum += e;
            sS[r * SSTR + lane + j * 32] = e;
        }
#pragma unroll
        for (int off = 16; off > 0; off >>= 1) sum += __shfl_xor_sync(0xffffffffu, sum, off);
        if (lane == 0) sDen[r] = sum;
    }
    __syncthreads();

    // ---- phase 3: O = P @ V (tf32 mma; V loaded fp16->fp32 in regs) ----
    {
        int wm2 = (wid & 1) * 16;
        int wn2 = (wid >> 1) * 16;
        float acc2[2][4];
#pragma unroll
        for (int j = 0; j < 2; j++)
#pragma unroll
            for (int c = 0; c < 4; c++) acc2[j][c] = 0.f;

        uint32_t aS = sSb + (wm2 + (g & 1) * 8 + rl) * (SSTR * 4) + (g >> 1) * 16;
#pragma unroll
        for (int ks = 0; ks < 24; ks++) {
            uint32_t af[4];
            LDSM_X4(af[0], af[1], af[2], af[3], aS + ks * 32);
            int k0 = ks * 8 + (lane & 3);
            int nb = wn2 + (lane >> 2);
            uint32_t bf[2][2];
#pragma unroll
            for (int nt = 0; nt < 2; nt++) {
                float b0 = __half2float(sKV[k0 * HSTR + nb + nt * 8]);
                float b1 = __half2float(sKV[(k0 + 4) * HSTR + nb + nt * 8]);
                bf[nt][0] = __float_as_uint(b0);
                bf[nt][1] = __float_as_uint(b1);
            }
#pragma unroll
            for (int nt = 0; nt < 2; nt++)
                MMA_TF32(acc2[nt], af, bf[nt]);
        }

        int r0o = wm2 + (lane >> 2);
        int r1o = r0o + 8;
        float inv0 = 1.f / sDen[r0o];
        float inv1 = 1.f / sDen[r1o];
        __half* ob0 = o + ((long)(b * SS + q0 + r0o)) * DD + h * DH;
        __half* ob1 = o + ((long)(b * SS + q0 + r1o)) * DD + h * DH;
#pragma unroll
        for (int nt = 0; nt < 2; nt++) {
            int col = wn2 + nt * 8 + 2 * (lane & 3);
            *(__half2*)(ob0 + col) = __floats2half2_rn(acc2[nt][0] * inv0, acc2[nt][1] * inv0);
            *(__half2*)(ob1 + col) = __floats2half2_rn(acc2[nt][2] * inv1, acc2[nt][3] * inv1);
        }
    }
}

// ---------------- launch ----------------
extern "C" void kernel_launch(void* const* d_in, const int* in_sizes, int n_in,
                              void* d_out, int out_size)
{
    const float* x     = (const float*)d_in[0];
    const int*   am    = (const int*)  d_in[1];
    const float* w_in  = (const float*)d_in[2];
    const float* b_in  = (const float*)d_in[3];
    const float* w_out = (const float*)d_in[4];
    const float* b_out = (const float*)d_in[5];
    const float* g1    = (const float*)d_in[6];
    const float* bl1   = (const float*)d_in[7];
    const float* g2    = (const float*)d_in[8];
    const float* bl2   = (const float*)d_in[9];
    const float* w1    = (const float*)d_in[10];
    const float* b1    = (const float*)d_in[11];
    const float* w2    = (const float*)d_in[12];
    const float* b2    = (const float*)d_in[13];
    float* out = (float*)d_out;

    void *p_hln, *p_qkv, *p_o, *p_x1, *p_h2, *p_wh;
    cudaGetSymbolAddress(&p_hln, g_hln);
    cudaGetSymbolAddress(&p_qkv, g_qkvh);
    cudaGetSymbolAddress(&p_o,   g_o);
    cudaGetSymbolAddress(&p_x1,  g_x1);
    cudaGetSymbolAddress(&p_h2,  g_h2);
    cudaGetSymbolAddress(&p_wh,  g_wh);
    __half* hln  = (__half*)p_hln;
    __half* qkvh = (__half*)p_qkv;
    __half* o    = (__half*)p_o;
    float*  x1   = (float*)p_x1;
    __half* h2   = (__half*)p_h2;
    __half* wh   = (__half*)p_wh;

    cudaFuncSetAttribute(gemm_h<false, false, true >, cudaFuncAttributeMaxDynamicSharedMemorySize, GEMM_SMEM);
    cudaFuncSetAttribute(gemm_h<false, true,  false>, cudaFuncAttributeMaxDynamicSharedMemorySize, GEMM_SMEM);
    cudaFuncSetAttribute(gemm_h<true,  false, true >, cudaFuncAttributeMaxDynamicSharedMemorySize, GEMM_SMEM);
    cudaFuncSetAttribute(attn_mma, cudaFuncAttributeMaxDynamicSharedMemorySize, ATTN_SMEM);

    // 0. all weights -> fp16
    wprep_kernel<<<WTOTAL / (256 * 4), 256>>>(w_in, w_out, w1, w2);
    // 1. LN1 -> fp16
    ln_kernel<<<ROWS, 256>>>(x, g1, bl1, hln);
    // 2. qkv = hln @ w_in^T + b_in   (fp16 mma, fp16 out)
    gemm_h<false, false, true><<<dim3(3 * DD / 128, ROWS / 128), 256, GEMM_SMEM>>>(hln, wh + OFF_WIN, b_in, nullptr, qkvh, ROWS, 3 * DD, DD);
    // 3. attention -> o (fp16)   (3 CTAs/SM)
    attn_mma<<<dim3(SS / QT, BB * HH), 256, ATTN_SMEM>>>(qkvh, am, o);
    // 4. x1 = x + o @ w_out^T + b_out   (fp16 mma, fp32 out)
    gemm_h<false, true, false><<<dim3(DD / 128, ROWS / 128), 256, GEMM_SMEM>>>(o, wh + OFF_WOUT, b_out, x, x1, ROWS, DD, DD);
    // 5. LN2 -> fp16
    ln_kernel<<<ROWS, 256>>>(x1, g2, bl2, hln);
    // 6. h2 = gelu(hln @ w1^T + b1)   (fp16 mma, fp16 out)
    gemm_h<true, false, true><<<dim3(FF / 128, ROWS / 128), 256, GEMM_SMEM>>>(hln, wh + OFF_W1, b1, nullptr, h2, ROWS, FF, DD);
    // 7. out = x1 + h2 @ w2^T + b2   (fp16 mma, fp32 out)
    gemm_h<false, true, false><<<dim3(DD / 128, ROWS / 128), 256, GEMM_SMEM>>>(h2, wh + OFF_W2, b2, x1, out, ROWS, DD, FF);
}

// round 16
// speedup vs baseline: 1.9082x; 1.0239x over previous
#include <cuda_runtime.h>
#include <cuda_fp16.h>
#include <math.h>
#include <cstdint>

// Problem constants
#define BB 2
#define SS 2048
#define DD 1024
#define HH 16
#define DH 64
#define FF 4096
#define ROWS (BB*SS)          // 4096
#define WINDOW 128
#define NGLOB 16
#define NEGH -60000.0f        // fp16-finite mask value (exp -> 0)

// input-ordered offsets inside g_wh (all weights fp16)
#define OFF_WIN  0
#define OFF_WOUT (3*DD*DD)
#define OFF_W1   (OFF_WOUT + DD*DD)
#define OFF_W2   (OFF_W1 + FF*DD)
#define WTOTAL   (OFF_W2 + DD*FF)

// ---------------- scratch ----------------
__device__ __half g_hln[ROWS * DD];         // LN outputs (fp16)
__device__ __half g_qkvh[ROWS * 3 * DD];    // qkv projection (fp16)
__device__ __half g_o  [ROWS * DD];         // attention output (fp16)
__device__ float  g_x1 [ROWS * DD];         // x + attn residual (fp32)
__device__ __half g_h2 [ROWS * FF];         // gelu hidden (fp16)
__device__ __half g_wh [WTOTAL];            // fp16 weights

// ---------------- helpers ----------------
__device__ __forceinline__ uint32_t smem_u32(const void* p) {
    uint32_t a;
    asm("{ .reg .u64 t; cvta.to.shared.u64 t, %1; cvt.u32.u64 %0, t; }" : "=r"(a) : "l"(p));
    return a;
}
#define CP_ASYNC16(sdst, gsrc) \
    asm volatile("cp.async.cg.shared.global [%0], [%1], 16;" :: "r"(sdst), "l"(gsrc))
#define CP_COMMIT() asm volatile("cp.async.commit_group;" ::: "memory")
#define CP_WAIT1()  asm volatile("cp.async.wait_group 1;" ::: "memory")

#define LDSM_X4(r0, r1, r2, r3, addr) \
    asm volatile("ldmatrix.sync.aligned.m8n8.x4.shared.b16 {%0,%1,%2,%3}, [%4];" \
        : "=r"(r0), "=r"(r1), "=r"(r2), "=r"(r3) : "r"(addr))

#define LDSM_X4_T(r0, r1, r2, r3, addr) \
    asm volatile("ldmatrix.sync.aligned.m8n8.x4.trans.shared.b16 {%0,%1,%2,%3}, [%4];" \
        : "=r"(r0), "=r"(r1), "=r"(r2), "=r"(r3) : "r"(addr))

#define MMA_F16(c, a, b) \
    asm volatile("mma.sync.aligned.m16n8k16.row.col.f32.f16.f16.f32 " \
        "{%0,%1,%2,%3}, {%4,%5,%6,%7}, {%8,%9}, {%0,%1,%2,%3};" \
        : "+f"((c)[0]), "+f"((c)[1]), "+f"((c)[2]), "+f"((c)[3]) \
        : "r"((a)[0]), "r"((a)[1]), "r"((a)[2]), "r"((a)[3]), \
          "r"((b)[0]), "r"((b)[1]))

// ---------------- weight prep: all four -> fp16 ----------------
__global__ __launch_bounds__(256) void wprep_kernel(const float* __restrict__ w_in,
                                                    const float* __restrict__ w_out,
                                                    const float* __restrict__ w1,
                                                    const float* __restrict__ w2)
{
    long i = ((long)blockIdx.x * 256 + threadIdx.x) * 4;
    float4 v;
    if (i < OFF_WOUT)      v = *(const float4*)(w_in + i);
    else if (i < OFF_W1)   v = *(const float4*)(w_out + (i - OFF_WOUT));
    else if (i < OFF_W2)   v = *(const float4*)(w1 + (i - OFF_W1));
    else                   v = *(const float4*)(w2 + (i - OFF_W2));
    __half2 p0 = __floats2half2_rn(v.x, v.y);
    __half2 p1 = __floats2half2_rn(v.z, v.w);
    uint2 pk = make_uint2(*(uint32_t*)&p0, *(uint32_t*)&p1);
    *(uint2*)(g_wh + i) = pk;
}

#define RSTR 144                            // smem row stride bytes
#define STG  (128 * RSTR)                   // 18432 per matrix per stage
#define NSTAGES 3
#define GEMM_SMEM (2 * NSTAGES * STG)       // 110592

// ---------------- fp16 GEMM: CTA 128x128, BK=64 halves, 8 warps 2Mx4N ----------------
template <bool GELU, bool RES, bool OUTH>
__global__ __launch_bounds__(256, 2) void gemm_h(const __half* __restrict__ A,
                                                 const __half* __restrict__ W,
                                                 const float* __restrict__ bias,
                                                 const float* __restrict__ res,
                                                 void* __restrict__ Cv,
                                                 int M, int N, int K)
{
    extern __shared__ char smem[];
    uint32_t sA = smem_u32(smem);
    uint32_t sB = sA + NSTAGES * STG;

    int tid = threadIdx.x;
    int lane = tid & 31, wid = tid >> 5;
    int m0 = blockIdx.y * 128;
    int n0 = blockIdx.x * 128;
    int wm = (wid & 1) * 64;
    int wn = (wid >> 1) * 32;

    int r0 = tid >> 3;
    int c16 = tid & 7;
    const __half* Agp = A + (long)(m0 + r0) * K + c16 * 8;
    const __half* Bgp = W + (long)(n0 + r0) * K + c16 * 8;
    uint32_t sa = sA + r0 * RSTR + c16 * 16;
    uint32_t sb = sB + r0 * RSTR + c16 * 16;

#define ISSUE_STAGE(s) do { \
    long k0g = (long)(s) * 64; \
    uint32_t so = ((s) % NSTAGES) * STG; \
    _Pragma("unroll") \
    for (int i_ = 0; i_ < 4; i_++) { \
        CP_ASYNC16(sa + so + i_ * (32 * RSTR), Agp + (long)(32 * i_) * K + k0g); \
        CP_ASYNC16(sb + so + i_ * (32 * RSTR), Bgp + (long)(32 * i_) * K + k0g); \
    } \
    CP_COMMIT(); } while (0)

    int g = lane >> 3;
    int rl = lane & 7;
    uint32_t aoff = (uint32_t)(((g & 1) * 8 + rl + wm) * RSTR + (g >> 1) * 16);
    uint32_t boff = (uint32_t)(((g >> 1) * 8 + rl + wn) * RSTR + (g & 1) * 16);

    float acc[4][4][4];
#pragma unroll
    for (int i = 0; i < 4; i++)
#pragma unroll
        for (int j = 0; j < 4; j++)
#pragma unroll
            for (int c = 0; c < 4; c++) acc[i][j][c] = 0.f;

    int nIter = K >> 6;
    ISSUE_STAGE(0);
    ISSUE_STAGE(1);

    for (int it = 0; it < nIter; it++) {
        CP_WAIT1();
        __syncthreads();
        if (it + 2 < nIter) { ISSUE_STAGE(it + 2); } else { CP_COMMIT(); }

        uint32_t slot = (uint32_t)((it % NSTAGES) * STG);
        uint32_t abase = sA + slot + aoff;
        uint32_t bbase = sB + slot + boff;
#pragma unroll
        for (int ks = 0; ks < 4; ks++) {
            uint32_t af[4][4], bf[4][2];
#pragma unroll
            for (int mi = 0; mi < 4; mi++)
                LDSM_X4(af[mi][0], af[mi][1], af[mi][2], af[mi][3],
                        abase + mi * (16 * RSTR) + ks * 32);
#pragma unroll
            for (int p = 0; p < 2; p++)
                LDSM_X4(bf[2*p][0], bf[2*p][1], bf[2*p+1][0], bf[2*p+1][1],
                        bbase + p * (16 * RSTR) + ks * 32);
#pragma unroll
            for (int mi = 0; mi < 4; mi++)
#pragma unroll
                for (int ni = 0; ni < 4; ni++)
                    MMA_F16(acc[mi][ni], af[mi], bf[ni]);
        }
    }
#undef ISSUE_STAGE

#pragma unroll
    for (int mi = 0; mi < 4; mi++) {
        long r_lo = m0 + wm + mi * 16 + (lane >> 2);
        long r_hi = r_lo + 8;
#pragma unroll
        for (int ni = 0; ni < 4; ni++) {
            int col = n0 + wn + ni * 8 + (lane & 3) * 2;
            float2 bv = *(const float2*)(bias + col);
            float v0 = acc[mi][ni][0] + bv.x;
            float v1 = acc[mi][ni][1] + bv.y;
            float v2 = acc[mi][ni][2] + bv.x;
            float v3 = acc[mi][ni][3] + bv.y;
            if (RES) {
                float2 rr0 = *(const float2*)(res + r_lo * N + col);
                float2 rr1 = *(const float2*)(res + r_hi * N + col);
                v0 += rr0.x; v1 += rr0.y; v2 += rr1.x; v3 += rr1.y;
            }
            if (GELU) {
                v0 = 0.5f * v0 * (1.0f + erff(v0 * 0.70710678118654752f));
                v1 = 0.5f * v1 * (1.0f + erff(v1 * 0.70710678118654752f));
                v2 = 0.5f * v2 * (1.0f + erff(v2 * 0.70710678118654752f));
                v3 = 0.5f * v3 * (1.0f + erff(v3 * 0.70710678118654752f));
            }
            if (OUTH) {
                __half* C = (__half*)Cv;
                *(__half2*)(C + r_lo * N + col) = __floats2half2_rn(v0, v1);
                *(__half2*)(C + r_hi * N + col) = __floats2half2_rn(v2, v3);
            } else {
                float* C = (float*)Cv;
                *(float2*)(C + r_lo * N + col) = make_float2(v0, v1);
                *(float2*)(C + r_hi * N + col) = make_float2(v2, v3);
            }
        }
    }
}

// ---------------- LayerNorm (fp32 in, fp16 out; float4 vectorized) ----------------
__global__ __launch_bounds__(256) void ln_kernel(const float* __restrict__ x,
                                                 const float* __restrict__ g,
                                                 const float* __restrict__ bt,
                                                 __half* __restrict__ out)
{
    int row = blockIdx.x;
    const float* xr = x + (long)row * DD;
    float4 v = *(const float4*)(xr + threadIdx.x * 4);
    float s  = v.x + v.y + v.z + v.w;
    float s2 = v.x * v.x + v.y * v.y + v.z * v.z + v.w * v.w;
    int lane = threadIdx.x & 31, warp = threadIdx.x >> 5;
#pragma unroll
    for (int off = 16; off > 0; off >>= 1) {
        s  += __shfl_xor_sync(0xffffffffu, s,  off);
        s2 += __shfl_xor_sync(0xffffffffu, s2, off);
    }
    __shared__ float sm[8], sm2[8];
    if (lane == 0) { sm[warp] = s; sm2[warp] = s2; }
    __syncthreads();
    if (threadIdx.x == 0) {
        float a = 0.f, b = 0.f;
#pragma unroll
        for (int i = 0; i < 8; i++) { a += sm[i]; b += sm2[i]; }
        float mean = a * (1.0f / DD);
        float var  = b * (1.0f / DD) - mean * mean;
        sm[0] = mean;
        sm2[0] = rsqrtf(var + 1e-5f);
    }
    __syncthreads();
    float mean = sm[0], inv = sm2[0];
    float4 gv = *(const float4*)(g  + threadIdx.x * 4);
    float4 bv = *(const float4*)(bt + threadIdx.x * 4);
    float r0 = (v.x - mean) * inv * gv.x + bv.x;
    float r1 = (v.y - mean) * inv * gv.y + bv.y;
    float r2 = (v.z - mean) * inv * gv.z + bv.z;
    float r3 = (v.w - mean) * inv * gv.w + bv.w;
    __half2 h0 = __floats2half2_rn(r0, r1);
    __half2 h1 = __floats2half2_rn(r2, r3);
    uint2 pk = make_uint2(*(uint32_t*)&h0, *(uint32_t*)&h1);
    *(uint2*)(out + (long)row * DD + threadIdx.x * 4) = pk;
}

// ---------------- mma-tiled sparse attention (all fp16 tiles) ----------------
// QT=32, KP=192. Q/K/V fp16 (HSTR=72 halves), P fp16 (SSTR=200 halves).
// Phase1 fp16 mma (4 k16). Phase3 fp16 mma with ldmatrix.trans on V (12 k16).
#define QT 32
#define KP 192
#define HSTR 72                  // halves per row (144B)
#define SSTR 200                 // halves per row (400B; 400%128=16 -> LDSM clean)
// smem bytes: Qh 4608 | KVh 27648 | Sh 12800 | am 768 | den 128 | lo/hi 1536
#define ATTN_SMEM (4608 + 27648 + 12800 + 768 + 128 + 1536)   // 47488

__global__ __launch_bounds__(256, 3) void attn_mma(const __half* __restrict__ qkv,
                                                   const int* __restrict__ am,
                                                   __half* __restrict__ o)
{
    extern __shared__ char sm8[];
    __half* sQh = (__half*)sm8;                    // 32 x 72
    __half* sKV = (__half*)(sm8 + 4608);           // 192 x 72 (K, then V)
    __half* sSh = (__half*)(sm8 + 4608 + 27648);   // 32 x 200 (fp16 scores/probs)
    float*  sAm = (float*)(sm8 + 4608 + 27648 + 12800);
    float*  sDen = sAm + KP;
    int* sLo = (int*)(sDen + QT);
    int* sHi = sLo + KP;

    uint32_t sQb = smem_u32(sQh);
    uint32_t sKb = smem_u32(sKV);
    uint32_t sSb = smem_u32(sSh);

    int tid = threadIdx.x;
    int lane = tid & 31, wid = tid >> 5;
    int q0 = blockIdx.x * QT;
    int h = blockIdx.y & 15;
    int b = blockIdx.y >> 4;

    int koff = max(0, q0 - WINDOW - NGLOB);
    int NK = min(KP - 16, q0 + QT);          // min(176, q0+32)

    const __half* qb = qkv + ((long)b * SS) * (3 * DD) + h * DH;

    // ---- load Q fp16 ----
    {
        int row = tid >> 3, ch = tid & 7;
        uint4 v = *(const uint4*)(qb + (long)(q0 + row) * (3 * DD) + ch * 8);
        *(uint4*)(sQh + row * HSTR + ch * 8) = v;
    }
    // ---- load K fp16 ----
#pragma unroll
    for (int t = 0; t < 6; t++) {
        int f = tid + t * 256;
        int idx = f >> 3, ch = f & 7;
        uint4 v = make_uint4(0, 0, 0, 0);
        if (idx < NK) {
            int key = idx + (idx < NGLOB ? 0 : koff);
            v = *(const uint4*)(qb + (long)key * (3 * DD) + DD + ch * 8);
        }
        *(uint4*)(sKV + idx * HSTR + ch * 8) = v;
    }
    if (tid < KP) {
        int idx = tid;
        float a = NEGH;
        int lo = 0x7fffffff, hi = 0x7fffffff;
        if (idx < NK) {
            int key = idx + (idx < NGLOB ? 0 : koff);
            a = (am[b * SS + key] == 0) ? NEGH : 0.f;
            lo = key;
            hi = (idx < NGLOB) ? 0x7fffffff : key + WINDOW;
        }
        sAm[idx] = a;
        sLo[idx] = lo;
        sHi[idx] = hi;
    }
    __syncthreads();

    int g = lane >> 3;
    int rl = lane & 7;
    // ---- phase 1: S = Q @ K^T (fp16 mma; warps 2M x 4N, 16q x 48k) ----
    int wm = (wid & 1) * 16;
    int wn = (wid >> 1) * 48;
    {
        float acc[6][4];
#pragma unroll
        for (int j = 0; j < 6; j++)
#pragma unroll
            for (int c = 0; c < 4; c++) acc[j][c] = 0.f;

        uint32_t aQ = sQb + (wm + (g & 1) * 8 + rl) * 144 + (g >> 1) * 16;
        uint32_t bK = sKb + (wn + (g >> 1) * 8 + rl) * 144 + (g & 1) * 16;
#pragma unroll
        for (int ks = 0; ks < 4; ks++) {
            uint32_t af[4], bf[6][2];
            LDSM_X4(af[0], af[1], af[2], af[3], aQ + ks * 32);
#pragma unroll
            for (int p = 0; p < 3; p++)
                LDSM_X4(bf[2*p][0], bf[2*p][1], bf[2*p+1][0], bf[2*p+1][1],
                        bK + p * (16 * 144) + ks * 32);
#pragma unroll
            for (int nt = 0; nt < 6; nt++)
                MMA_F16(acc[nt], af, bf[nt]);
        }

        int r0 = wm + (lane >> 2);
        int r1 = r0 + 8;
        int qa0 = q0 + r0, qa1 = q0 + r1;
#pragma unroll
        for (int nt = 0; nt < 6; nt++) {
            int col = wn + nt * 8 + 2 * (lane & 3);
            float f0, f1, f2, f3;
            {
                int c0 = col, c1 = col + 1;
                int lo0 = sLo[c0], hi0 = sHi[c0];
                int lo1 = sLo[c1], hi1 = sHi[c1];
                float a0 = sAm[c0], a1 = sAm[c1];
                f0 = (qa0 >= lo0 && qa0 <= hi0) ? acc[nt][0] * 0.125f + a0 : NEGH;
                f1 = (qa0 >= lo1 && qa0 <= hi1) ? acc[nt][1] * 0.125f + a1 : NEGH;
                f2 = (qa1 >= lo0 && qa1 <= hi0) ? acc[nt][2] * 0.125f + a0 : NEGH;
                f3 = (qa1 >= lo1 && qa1 <= hi1) ? acc[nt][3] * 0.125f + a1 : NEGH;
            }
            *(__half2*)(sSh + r0 * SSTR + col) = __floats2half2_rn(f0, f1);
            *(__half2*)(sSh + r1 * SSTR + col) = __floats2half2_rn(f2, f3);
        }
    }
    __syncthreads();

    // ---- load V fp16 (overwrites K region, same layout) ----
#pragma unroll
    for (int t = 0; t < 6; t++) {
        int f = tid + t * 256;
        int idx = f >> 3, ch = f & 7;
        uint4 v = make_uint4(0, 0, 0, 0);
        if (idx < NK) {
            int key = idx + (idx < NGLOB ? 0 : koff);
            v = *(const uint4*)(qb + (long)key * (3 * DD) + 2 * DD + ch * 8);
        }
        *(uint4*)(sKV + idx * HSTR + ch * 8) = v;
    }

    // ---- phase 2: softmax rows (warp w: rows w*4 .. w*4+3; half2 IO) ----
#pragma unroll
    for (int i = 0; i < 4; i++) {
        int r = wid * 4 + i;
        float2 v[3];
#pragma unroll
        for (int j = 0; j < 3; j++)
            v[j] = __half22float2(*(__half2*)(sSh + r * SSTR + 2 * lane + j * 64));
        float mx = fmaxf(fmaxf(fmaxf(v[0].x, v[0].y), fmaxf(v[1].x, v[1].y)),
                         fmaxf(v[2].x, v[2].y));
#pragma unroll
        for (int off = 16; off > 0; off >>= 1) mx = fmaxf(mx, __shfl_xor_sync(0xffffffffu, mx, off));
        float sum = 0.f;
#pragma unroll
        for (int j = 0; j < 3; j++) {
            float e0 = __expf(v[j].x - mx);
            float e1 = __expf(v[j].y - mx);
            __half2 hp = __floats2half2_rn(e0, e1);
            *(__half2*)(sSh + r * SSTR + 2 * lane + j * 64) = hp;
            float2 back = __half22float2(hp);
            sum += back.x + back.y;
        }
#pragma unroll
        for (int off = 16; off > 0; off >>= 1) sum += __shfl_xor_sync(0xffffffffu, sum, off);
        if (lane == 0) sDen[r] = sum;
    }
    __syncthreads();

    // ---- phase 3: O = P @ V (fp16 mma; V B-frags via ldmatrix.trans) ----
    {
        int wm2 = (wid & 1) * 16;
        int wn2 = (wid >> 1) * 16;
        float acc2[2][4];
#pragma unroll
        for (int j = 0; j < 2; j++)
#pragma unroll
            for (int c = 0; c < 4; c++) acc2[j][c] = 0.f;

        uint32_t aP = sSb + (wm2 + (g & 1) * 8 + rl) * (SSTR * 2) + (g >> 1) * 16;
        // trans B: lane group g: key_sub=(g&1)*8, dim_blk=(g>>1)*8
        uint32_t bV = sKb + (uint32_t)(((g & 1) * 8 + rl) * (HSTR * 2) + (wn2 + (g >> 1) * 8) * 2);
#pragma unroll
        for (int ks = 0; ks < 12; ks++) {
            uint32_t af[4], bf[2][2];
            LDSM_X4(af[0], af[1], af[2], af[3], aP + ks * 32);
            LDSM_X4_T(bf[0][0], bf[0][1], bf[1][0], bf[1][1],
                      bV + ks * (16 * HSTR * 2));
            MMA_F16(acc2[0], af, bf[0]);
            MMA_F16(acc2[1], af, bf[1]);
        }

        int r0o = wm2 + (lane >> 2);
        int r1o = r0o + 8;
        float inv0 = 1.f / sDen[r0o];
        float inv1 = 1.f / sDen[r1o];
        __half* ob0 = o + ((long)(b * SS + q0 + r0o)) * DD + h * DH;
        __half* ob1 = o + ((long)(b * SS + q0 + r1o)) * DD + h * DH;
#pragma unroll
        for (int nt = 0; nt < 2; nt++) {
            int col = wn2 + nt * 8 + 2 * (lane & 3);
            *(__half2*)(ob0 + col) = __floats2half2_rn(acc2[nt][0] * inv0, acc2[nt][1] * inv0);
            *(__half2*)(ob1 + col) = __floats2half2_rn(acc2[nt][2] * inv1, acc2[nt][3] * inv1);
        }
    }
}

// ---------------- launch ----------------
extern "C" void kernel_launch(void* const* d_in, const int* in_sizes, int n_in,
                              void* d_out, int out_size)
{
    const float* x     = (const float*)d_in[0];
    const int*   am    = (const int*)  d_in[1];
    const float* w_in  = (const float*)d_in[2];
    const float* b_in  = (const float*)d_in[3];
    const float* w_out = (const float*)d_in[4];
    const float* b_out = (const float*)d_in[5];
    const float* g1    = (const float*)d_in[6];
    const float* bl1   = (const float*)d_in[7];
    const float* g2    = (const float*)d_in[8];
    const float* bl2   = (const float*)d_in[9];
    const float* w1    = (const float*)d_in[10];
    const float* b1    = (const float*)d_in[11];
    const float* w2    = (const float*)d_in[12];
    const float* b2    = (const float*)d_in[13];
    float* out = (float*)d_out;

    void *p_hln, *p_qkv, *p_o, *p_x1, *p_h2, *p_wh;
    cudaGetSymbolAddress(&p_hln, g_hln);
    cudaGetSymbolAddress(&p_qkv, g_qkvh);
    cudaGetSymbolAddress(&p_o,   g_o);
    cudaGetSymbolAddress(&p_x1,  g_x1);
    cudaGetSymbolAddress(&p_h2,  g_h2);
    cudaGetSymbolAddress(&p_wh,  g_wh);
    __half* hln  = (__half*)p_hln;
    __half* qkvh = (__half*)p_qkv;
    __half* o    = (__half*)p_o;
    float*  x1   = (float*)p_x1;
    __half* h2   = (__half*)p_h2;
    __half* wh   = (__half*)p_wh;

    cudaFuncSetAttribute(gemm_h<false, false, true >, cudaFuncAttributeMaxDynamicSharedMemorySize, GEMM_SMEM);
    cudaFuncSetAttribute(gemm_h<false, true,  false>, cudaFuncAttributeMaxDynamicSharedMemorySize, GEMM_SMEM);
    cudaFuncSetAttribute(gemm_h<true,  false, true >, cudaFuncAttributeMaxDynamicSharedMemorySize, GEMM_SMEM);
    cudaFuncSetAttribute(attn_mma, cudaFuncAttributeMaxDynamicSharedMemorySize, ATTN_SMEM);

    // 0. all weights -> fp16
    wprep_kernel<<<WTOTAL / (256 * 4), 256>>>(w_in, w_out, w1, w2);
    // 1. LN1 -> fp16
    ln_kernel<<<ROWS, 256>>>(x, g1, bl1, hln);
    // 2. qkv = hln @ w_in^T + b_in   (fp16 mma, fp16 out)
    gemm_h<false, false, true><<<dim3(3 * DD / 128, ROWS / 128), 256, GEMM_SMEM>>>(hln, wh + OFF_WIN, b_in, nullptr, qkvh, ROWS, 3 * DD, DD);
    // 3. attention -> o (fp16, 3 CTAs/SM)
    attn_mma<<<dim3(SS / QT, BB * HH), 256, ATTN_SMEM>>>(qkvh, am, o);
    // 4. x1 = x + o @ w_out^T + b_out   (fp16 mma, fp32 out)
    gemm_h<false, true, false><<<dim3(DD / 128, ROWS / 128), 256, GEMM_SMEM>>>(o, wh + OFF_WOUT, b_out, x, x1, ROWS, DD, DD);
    // 5. LN2 -> fp16
    ln_kernel<<<ROWS, 256>>>(x1, g2, bl2, hln);
    // 6. h2 = gelu(hln @ w1^T + b1)   (fp16 mma, fp16 out)
    gemm_h<true, false, true><<<dim3(FF / 128, ROWS / 128), 256, GEMM_SMEM>>>(hln, wh + OFF_W1, b1, nullptr, h2, ROWS, FF, DD);
    // 7. out = x1 + h2 @ w2^T + b2   (fp16 mma, fp32 out)
    gemm_h<false, true, false><<<dim3(DD / 128, ROWS / 128), 256, GEMM_SMEM>>>(h2, wh + OFF_W2, b2, x1, out, ROWS, DD, FF);
}